// round 5
// baseline (speedup 1.0000x reference)
#include <cuda_runtime.h>
#include <cuda_bf16.h>
#include <math.h>
#include <cstdint>

#define H     300
#define G     900
#define NB    1024
#define LSEQ  64
#define NTHREADS 320
#define NNODES 49152

// ---- input GEMM config (proven round-4 path) ----
#define KP  960
#define NP  1024
#define MT  128
#define NKB2 (KP / 32)
#define SROW 80

// ---- recurrent mma config ----
#define GP    304            // padded rows per gate (19 m16-tiles)
#define RROWS 912            // 3*GP
#define RMT   57             // m16 tiles
#define RKC   40             // k16 chunks: 20 (W_hi) + 20 (W_lo)
#define WCHB  (RROWS * 48)   // chunk bytes in smem (48B/row stride)
#define HSS   648            // h-split smem row stride (bf16)
#define HFS   304            // h fp32 smem row stride
#define RBT   16             // graphs per CTA

// dynamic smem layout for k_recur_mma (bytes)
#define SM_W    0
#define SM_D    (2 * WCHB)                  // 87552
#define SM_HS   (SM_D + RROWS * 16 * 4)     // 145920
#define SM_HF   (SM_HS + RBT * HSS * 2)     // 166656
#define SM_MISC (SM_HF + RBT * HFS * 4)     // 186112
#define SM_BH   (SM_MISC + 128)             // 186240: bhh[900]
#define SM_BI   (SM_BH + 3600)              // 189840: bih[900]
#define SM_TOT  (SM_BI + 3600)              // 193440

__device__ __forceinline__ float sigm(float x) { return 1.f / (1.f + __expf(-x)); }
__device__ __forceinline__ float tanh_fast(float x) {
    float s = 1.f / (1.f + __expf(-2.f * x));
    return 2.f * s - 1.f;
}
__device__ __forceinline__ uint32_t smem_u32(const void* p) {
    uint32_t a;
    asm("{ .reg .u64 t; cvta.to.shared.u64 t, %1; cvt.u32.u64 %0, t; }" : "=r"(a) : "l"(p));
    return a;
}
__device__ __forceinline__ float ldcs(const float* p) {
    float v; asm volatile("ld.global.cs.f32 %0, [%1];" : "=f"(v) : "l"(p)); return v;
}
__device__ __forceinline__ void stcs(float* p, float v) {
    asm volatile("st.global.cs.f32 [%0], %1;" :: "l"(p), "f"(v));
}

// ---------------- device scratch ----------------
__device__ __align__(16) __nv_bfloat16 g_abf[(size_t)NNODES * KP];    // A' = [hi|lo|hi]
__device__ __align__(16) __nv_bfloat16 g_bbf[2][(size_t)NP * KP];     // B' = [hi|hi|lo]
__device__ __align__(16) __nv_bfloat16 g_gwr[(size_t)2 * RKC * RROWS * 16]; // W_hh chunks
__device__ float g_xg[2][(size_t)NNODES * G];
__device__ float g_h0[NB * H];
__device__ int   g_sstart[NB];
__device__ int   g_slen[NB];

// ---------------- 1) segment bounds ----------------
__global__ void k_seg(const int* __restrict__ batch, const int* __restrict__ pos, int n) {
    int i = blockIdx.x * blockDim.x + threadIdx.x;
    if (i >= n) return;
    int b = batch[i];
    if (pos[i] == 0) g_sstart[b] = i;
    if (i == n - 1 || batch[i + 1] != b) g_slen[b] = pos[i] + 1;
}

// ---------------- 2) h0 = per-graph segment max ----------------
__global__ void __launch_bounds__(NTHREADS) k_h0(const float* __restrict__ node) {
    int b = blockIdx.x, h = threadIdx.x;
    if (h >= H) return;
    int s = g_sstart[b], l = g_slen[b];
    float m = -3.402823466e38f;
    for (int i = 0; i < l; ++i) m = fmaxf(m, node[(size_t)(s + i) * H + h]);
    g_h0[b * H + h] = m;
}

// ---------------- 3) A' = split-bf16 of relu(node + bias) ----------------
__global__ void k_convA(const float* __restrict__ node, const float* __restrict__ bias, int n) {
    size_t tot = (size_t)n * KP;
    for (size_t idx = (size_t)blockIdx.x * blockDim.x + threadIdx.x; idx < tot;
         idx += (size_t)gridDim.x * blockDim.x) {
        size_t i = idx / KP;
        int kp = (int)(idx - i * KP);
        __nv_bfloat16 o = __float2bfloat16(0.f);
        int k = -1; bool lo = false;
        if (kp < 300)                    { k = kp; }
        else if (kp >= 320 && kp < 620)  { k = kp - 320; lo = true; }
        else if (kp >= 640 && kp < 940)  { k = kp - 640; }
        if (k >= 0) {
            float m = node[i * H + k] + bias[k];
            m = m > 0.f ? m : 0.f;
            __nv_bfloat16 hi = __float2bfloat16(m);
            o = lo ? __float2bfloat16(m - __bfloat162float(hi)) : hi;
        }
        g_abf[idx] = o;
    }
}

// ---------------- 4) B' = split-bf16 of w_ih ----------------
__global__ void k_convB(const float* __restrict__ wif, const float* __restrict__ wib) {
    size_t tot = (size_t)2 * NP * KP;
    for (size_t idx = (size_t)blockIdx.x * blockDim.x + threadIdx.x; idx < tot;
         idx += (size_t)gridDim.x * blockDim.x) {
        int dir = (int)(idx / ((size_t)NP * KP));
        size_t r = idx - (size_t)dir * NP * KP;
        int g = (int)(r / KP), kp = (int)(r - (size_t)g * KP);
        __nv_bfloat16 o = __float2bfloat16(0.f);
        int k = -1; bool lo = false;
        if (kp < 300)                    { k = kp; }
        else if (kp >= 320 && kp < 620)  { k = kp - 320; }
        else if (kp >= 640 && kp < 940)  { k = kp - 640; lo = true; }
        if (k >= 0 && g < G) {
            const float* w = dir ? wib : wif;
            float v = w[(size_t)g * H + k];
            __nv_bfloat16 hi = __float2bfloat16(v);
            o = lo ? __float2bfloat16(v - __bfloat162float(hi)) : hi;
        }
        g_bbf[dir][r] = o;
    }
}

// ---------------- 5) W_hh -> chunked split layout [dir][kc][row][16] ----------------
// rows: gate*GP + j (zero-padded); kc<20: W_hi at k=kc*16+c; kc>=20: W_lo at k-320
__global__ void k_convW(const float* __restrict__ whf, const float* __restrict__ whb) {
    const int tot = 2 * RKC * RROWS * 16;
    for (int idx = blockIdx.x * blockDim.x + threadIdx.x; idx < tot;
         idx += gridDim.x * blockDim.x) {
        int dir = idx / (RKC * RROWS * 16);
        int r = idx % (RKC * RROWS * 16);
        int kc = r / (RROWS * 16);
        int rr = r % (RROWS * 16);
        int row = rr >> 4, c = rr & 15;
        int gate = row / GP, j = row % GP;
        int keff = kc * 16 + c;
        bool lo = keff >= 320;
        int k = lo ? keff - 320 : keff;
        __nv_bfloat16 o = __float2bfloat16(0.f);
        if (j < H && k < H) {
            const float* w = dir ? whb : whf;
            float v = w[(size_t)(gate * H + j) * H + k];
            __nv_bfloat16 hi = __float2bfloat16(v);
            o = lo ? __float2bfloat16(v - __bfloat162float(hi)) : hi;
        }
        g_gwr[idx] = o;
    }
}

// ---------------- 6) input GEMM via mma.sync (proven round-4) ----------------
__global__ void __launch_bounds__(256, 2) k_gemm_mma(const float* __restrict__ bih_f,
                                                     const float* __restrict__ bih_b) {
    __shared__ __align__(16) unsigned char sA[2][MT * SROW];
    __shared__ __align__(16) unsigned char sB[2][128 * SROW];
    const int tid = threadIdx.x, lane = tid & 31, wid = tid >> 5;
    const int dir = blockIdx.x >> 3, ntile = blockIdx.x & 7;
    const int m0 = blockIdx.y * MT, n0 = ntile * 128;
    const int wm = wid & 3, wn = wid >> 2;

    const __nv_bfloat16* __restrict__ A = g_abf + (size_t)m0 * KP;
    const __nv_bfloat16* __restrict__ B = g_bbf[dir] + (size_t)n0 * KP;
    const uint32_t sA0 = smem_u32(sA), sB0 = smem_u32(sB);

    float d[2][8][4];
#pragma unroll
    for (int mi = 0; mi < 2; ++mi)
#pragma unroll
        for (int ni = 0; ni < 8; ++ni)
#pragma unroll
            for (int e = 0; e < 4; ++e) d[mi][ni][e] = 0.f;

#define ISSUE_STAGE(kb) do {                                                        \
    int _buf = (kb) & 1;                                                            \
    _Pragma("unroll")                                                               \
    for (int _p = 0; _p < 2; ++_p) {                                                \
        int _u = _p * 256 + tid, _row = _u >> 2, _c = _u & 3;                       \
        const void* _ga = A + (size_t)_row * KP + (kb) * 32 + _c * 8;               \
        uint32_t _da = sA0 + _buf * (MT * SROW) + _row * SROW + _c * 16;            \
        asm volatile("cp.async.cg.shared.global [%0], [%1], 16;" :: "r"(_da), "l"(_ga)); \
        const void* _gb = B + (size_t)_row * KP + (kb) * 32 + _c * 8;               \
        uint32_t _db = sB0 + _buf * (128 * SROW) + _row * SROW + _c * 16;           \
        asm volatile("cp.async.cg.shared.global [%0], [%1], 16;" :: "r"(_db), "l"(_gb)); \
    }                                                                               \
    asm volatile("cp.async.commit_group;" ::: "memory");                            \
} while (0)

    ISSUE_STAGE(0);
    for (int kb = 0; kb < NKB2; ++kb) {
        if (kb + 1 < NKB2) {
            ISSUE_STAGE(kb + 1);
            asm volatile("cp.async.wait_group 1;" ::: "memory");
        } else {
            asm volatile("cp.async.wait_group 0;" ::: "memory");
        }
        __syncthreads();
        const uint32_t* a32 = (const uint32_t*)(sA[kb & 1]);
        const uint32_t* b32 = (const uint32_t*)(sB[kb & 1]);
#pragma unroll
        for (int ks = 0; ks < 2; ++ks) {
            uint32_t af[2][4];
#pragma unroll
            for (int mi = 0; mi < 2; ++mi) {
                int r0 = wm * 32 + mi * 16 + (lane >> 2);
                af[mi][0] = a32[r0 * 20 + ks * 8 + (lane & 3)];
                af[mi][1] = a32[(r0 + 8) * 20 + ks * 8 + (lane & 3)];
                af[mi][2] = a32[r0 * 20 + ks * 8 + 4 + (lane & 3)];
                af[mi][3] = a32[(r0 + 8) * 20 + ks * 8 + 4 + (lane & 3)];
            }
#pragma unroll
            for (int ni = 0; ni < 8; ++ni) {
                int cn = wn * 64 + ni * 8 + (lane >> 2);
                uint32_t b0 = b32[cn * 20 + ks * 8 + (lane & 3)];
                uint32_t b1 = b32[cn * 20 + ks * 8 + 4 + (lane & 3)];
#pragma unroll
                for (int mi = 0; mi < 2; ++mi) {
                    asm volatile(
                        "mma.sync.aligned.m16n8k16.row.col.f32.bf16.bf16.f32 "
                        "{%0,%1,%2,%3}, {%4,%5,%6,%7}, {%8,%9}, {%0,%1,%2,%3};"
                        : "+f"(d[mi][ni][0]), "+f"(d[mi][ni][1]),
                          "+f"(d[mi][ni][2]), "+f"(d[mi][ni][3])
                        : "r"(af[mi][0]), "r"(af[mi][1]), "r"(af[mi][2]), "r"(af[mi][3]),
                          "r"(b0), "r"(b1));
                }
            }
        }
        __syncthreads();
    }
#undef ISSUE_STAGE

    const float* __restrict__ bih = dir ? bih_b : bih_f;
    float* __restrict__ xg = g_xg[dir];
#pragma unroll
    for (int mi = 0; mi < 2; ++mi) {
        int r0 = m0 + wm * 32 + mi * 16 + (lane >> 2);
#pragma unroll
        for (int ni = 0; ni < 8; ++ni) {
            int g = n0 + wn * 64 + ni * 8 + (lane & 3) * 2;
            if (g < G) {
                float bg0 = bih[g], bg1 = bih[g + 1];
                *(float2*)(xg + (size_t)r0 * G + g) =
                    make_float2(d[mi][ni][0] + bg0, d[mi][ni][1] + bg1);
                *(float2*)(xg + (size_t)(r0 + 8) * G + g) =
                    make_float2(d[mi][ni][2] + bg0, d[mi][ni][3] + bg1);
            }
        }
    }
}

// ---------------- 7) recurrent GRU via mma.sync, weights streamed ----------------
__global__ void __launch_bounds__(256, 1) k_recur_mma(const float* __restrict__ bih_f,
                                                      const float* __restrict__ bih_b,
                                                      const float* __restrict__ bhh_f,
                                                      const float* __restrict__ bhh_b,
                                                      float* __restrict__ out) {
    extern __shared__ char smem[];
    float*           Dsm  = (float*)(smem + SM_D);
    uint32_t*        hs32 = (uint32_t*)(smem + SM_HS);
    __nv_bfloat16*   hsb  = (__nv_bfloat16*)(smem + SM_HS);
    float*           hf   = (float*)(smem + SM_HF);
    int*             sst  = (int*)(smem + SM_MISC);
    int*             sln  = sst + RBT;
    float*           sbhh = (float*)(smem + SM_BH);
    float*           sbih = (float*)(smem + SM_BI);

    const int tid = threadIdx.x, lane = tid & 31, wid = tid >> 5;
    const int dir = blockIdx.y;
    const int b0 = blockIdx.x * RBT;
    const uint32_t swb = smem_u32(smem);                  // wbuf base (SM_W = 0)
    const uint32_t* w32base = (const uint32_t*)smem;

    // ---- init ----
    if (tid < RBT) { sst[tid] = g_sstart[b0 + tid]; sln[tid] = g_slen[b0 + tid]; }
    for (int i = tid; i < RBT * HSS / 2; i += 256) hs32[i] = 0u;
    {
        const float* bhh = dir ? bhh_b : bhh_f;
        const float* bih = dir ? bih_b : bih_f;
        for (int i = tid; i < G; i += 256) { sbhh[i] = bhh[i]; sbih[i] = bih[i]; }
    }
    __syncthreads();   // hsplit zero before writing hi/lo into it
    for (int it = tid; it < RBT * H; it += 256) {
        int j = it >> 4, b = it & 15;
        float v = g_h0[(b0 + b) * H + j];
        hf[b * HFS + j] = v;
        __nv_bfloat16 hi = __float2bfloat16(v);
        hsb[b * HSS + j] = hi;
        hsb[b * HSS + 320 + j] = __float2bfloat16(v - __bfloat162float(hi));
    }
    __syncthreads();

    const __nv_bfloat16* __restrict__ gw = g_gwr + (size_t)dir * RKC * RROWS * 16;
    const float* __restrict__ xg = g_xg[dir];

#define ISSUE_W(kcmod, buf) do {                                                    \
    const __nv_bfloat16* _src = gw + (size_t)(kcmod) * RROWS * 16;                  \
    uint32_t _dst0 = swb + (buf) * WCHB;                                            \
    _Pragma("unroll")                                                               \
    for (int _p = 0; _p < 8; ++_p) {                                                \
        int _i = _p * 256 + tid;                                                    \
        if (_i < RROWS * 2) {                                                       \
            int _row = _i >> 1, _half = _i & 1;                                     \
            uint32_t _d = _dst0 + _row * 48 + _half * 16;                           \
            const void* _s = _src + _row * 16 + _half * 8;                          \
            asm volatile("cp.async.cg.shared.global [%0], [%1], 16;" :: "r"(_d), "l"(_s)); \
        }                                                                           \
    }                                                                               \
    asm volatile("cp.async.commit_group;" ::: "memory");                            \
} while (0)

    ISSUE_W(0, 0);
    int nextc = 1;

    for (int s = 0; s < LSEQ; ++s) {
        int t = dir ? (LSEQ - 1 - s) : s;
        float acc[8][2][4];
#pragma unroll
        for (int i = 0; i < 8; ++i)
#pragma unroll
            for (int nt = 0; nt < 2; ++nt)
#pragma unroll
                for (int e = 0; e < 4; ++e) acc[i][nt][e] = 0.f;

        for (int kc = 0; kc < RKC; ++kc) {
            asm volatile("cp.async.wait_group 0;" ::: "memory");
            __syncthreads();                         // chunk kc ready; prior mma done
            if (!(s == LSEQ - 1 && kc == RKC - 1)) { // prefetch next chunk (periodic)
                ISSUE_W(nextc, nextc & 1);
                nextc = (nextc + 1 == RKC) ? 0 : nextc + 1;
            }
            const uint32_t* w32 = w32base + (kc & 1) * (WCHB / 4);
            const int npass = (kc < 20) ? 2 : 1;
            const int hk0 = (kc < 20) ? kc * 8 : (kc - 20) * 8;
#pragma unroll 1
            for (int pass = 0; pass < npass; ++pass) {
                int hk = hk0 + pass * 160;           // u32 col: h_hi at 0, h_lo at +160
                uint32_t bfr[2][2];
#pragma unroll
                for (int nt = 0; nt < 2; ++nt) {
                    int nr = nt * 8 + (lane >> 2);
                    bfr[nt][0] = hs32[nr * (HSS / 2) + hk + (lane & 3)];
                    bfr[nt][1] = hs32[nr * (HSS / 2) + hk + 4 + (lane & 3)];
                }
#pragma unroll
                for (int i = 0; i < 8; ++i) {
                    int mt = wid + 8 * i;
                    if (mt < RMT) {
                        int r0 = mt * 16 + (lane >> 2);
                        uint32_t a0 = w32[r0 * 12 + (lane & 3)];
                        uint32_t a1 = w32[(r0 + 8) * 12 + (lane & 3)];
                        uint32_t a2 = w32[r0 * 12 + 4 + (lane & 3)];
                        uint32_t a3 = w32[(r0 + 8) * 12 + 4 + (lane & 3)];
#pragma unroll
                        for (int nt = 0; nt < 2; ++nt) {
                            asm volatile(
                                "mma.sync.aligned.m16n8k16.row.col.f32.bf16.bf16.f32 "
                                "{%0,%1,%2,%3}, {%4,%5,%6,%7}, {%8,%9}, {%0,%1,%2,%3};"
                                : "+f"(acc[i][nt][0]), "+f"(acc[i][nt][1]),
                                  "+f"(acc[i][nt][2]), "+f"(acc[i][nt][3])
                                : "r"(a0), "r"(a1), "r"(a2), "r"(a3),
                                  "r"(bfr[nt][0]), "r"(bfr[nt][1]));
                        }
                    }
                }
            }
        }

        // write hg preactivations to smem D[row][graph]
#pragma unroll
        for (int i = 0; i < 8; ++i) {
            int mt = wid + 8 * i;
            if (mt < RMT) {
                int r0 = mt * 16 + (lane >> 2);
#pragma unroll
                for (int nt = 0; nt < 2; ++nt) {
                    int c = nt * 8 + (lane & 3) * 2;
                    *(float2*)(Dsm + r0 * 16 + c) = make_float2(acc[i][nt][0], acc[i][nt][1]);
                    *(float2*)(Dsm + (r0 + 8) * 16 + c) = make_float2(acc[i][nt][2], acc[i][nt][3]);
                }
            }
        }
        __syncthreads();

        // pointwise GRU update
        for (int it = tid; it < RBT * H; it += 256) {
            int j = it >> 4, b = it & 15;
            bool valid = t < sln[b];
            size_t ni = (size_t)(sst[b] + t);
            float x0, x1, x2;
            if (valid) {
                const float* xr = xg + ni * G;
                x0 = ldcs(xr + j); x1 = ldcs(xr + H + j); x2 = ldcs(xr + 2 * H + j);
            } else {
                x0 = sbih[j]; x1 = sbih[H + j]; x2 = sbih[2 * H + j];
            }
            float hgr = Dsm[j * 16 + b];
            float hgz = Dsm[(GP + j) * 16 + b];
            float hgn = Dsm[(2 * GP + j) * 16 + b];
            float r  = sigm(x0 + hgr + sbhh[j]);
            float z  = sigm(x1 + hgz + sbhh[H + j]);
            float nn = tanh_fast(x2 + r * (hgn + sbhh[2 * H + j]));
            float hp = hf[b * HFS + j];
            float hv = (1.f - z) * nn + z * hp;
            hf[b * HFS + j] = hv;
            __nv_bfloat16 hi = __float2bfloat16(hv);
            hsb[b * HSS + j] = hi;
            hsb[b * HSS + 320 + j] = __float2bfloat16(hv - __bfloat162float(hi));
            if (valid) stcs(out + ni * (2 * H) + dir * H + j, hv);
        }
        __syncthreads();
    }
#undef ISSUE_W
}

// ---------------- host entry ----------------
extern "C" void kernel_launch(void* const* d_in, const int* in_sizes, int n_in,
                              void* d_out, int out_size) {
    const float* node   = (const float*)d_in[0];
    const int*   batch  = (const int*)d_in[1];
    const int*   pos    = (const int*)d_in[2];
    const float* bias   = (const float*)d_in[3];
    const float* w_ih_f = (const float*)d_in[4];
    const float* w_hh_f = (const float*)d_in[5];
    const float* b_ih_f = (const float*)d_in[6];
    const float* b_hh_f = (const float*)d_in[7];
    const float* w_ih_b = (const float*)d_in[8];
    const float* w_hh_b = (const float*)d_in[9];
    const float* b_ih_b = (const float*)d_in[10];
    const float* b_hh_b = (const float*)d_in[11];
    float* out = (float*)d_out;
    int n = in_sizes[0] / H;

    cudaFuncSetAttribute(k_recur_mma, cudaFuncAttributeMaxDynamicSharedMemorySize, SM_TOT);

    k_seg<<<(n + 255) / 256, 256>>>(batch, pos, n);
    k_h0<<<NB, NTHREADS>>>(node);
    k_convA<<<4096, 256>>>(node, bias, n);
    k_convB<<<2048, 256>>>(w_ih_f, w_ih_b);
    k_convW<<<1024, 256>>>(w_hh_f, w_hh_b);
    k_gemm_mma<<<dim3(16, n / MT), 256>>>(b_ih_f, b_ih_b);
    k_recur_mma<<<dim3(NB / RBT, 2), 256, SM_TOT>>>(b_ih_f, b_ih_b, b_hh_f, b_hh_b, out);
}

// round 6
// speedup vs baseline: 1.9100x; 1.9100x over previous
#include <cuda_runtime.h>
#include <cuda_bf16.h>
#include <math.h>
#include <cstdint>

#define H     300
#define G     900
#define NB    1024
#define LSEQ  64
#define NTHREADS 320
#define NNODES 49152

// ---- input GEMM config (proven round-4 path) ----
#define KP  960
#define NP  1024
#define MT  128
#define NKB2 (KP / 32)
#define SROW 80

// ---- recurrent mma config ----
#define GP    320                  // padded rows per gate (20 m16-tiles)
#define RROWS 960                  // 3*GP
#define RKC   38                   // k16 chunks: 19 (W_hi) + 19 (W_lo)
#define WSTG  (RROWS * 32)         // one stage: 960 rows x 32B = 30720
#define HSS   648                  // h-split smem row stride (bf16)
#define HFS   304                  // h fp32 smem row stride
#define RBT   16                   // graphs per CTA
#define RNT   384                  // 12 warps

// dynamic smem layout for k_recur_mma (bytes)
#define SM_W    0
#define SM_D    (4 * WSTG)                    // 122880
#define SM_HS   (SM_D + RROWS * 16 * 4)       // 184320
#define SM_HF   (SM_HS + RBT * HSS * 2)       // 205056
#define SM_BH   (SM_HF + RBT * HFS * 4)       // 224512
#define SM_BI   (SM_BH + 3600)                // 228112
#define SM_MISC (SM_BI + 3600)                // 231712
#define SM_TOT  (SM_MISC + 128)               // 231840 (<= 232448 opt-in)

__device__ __forceinline__ float sigm(float x) { return 1.f / (1.f + __expf(-x)); }
__device__ __forceinline__ float tanh_fast(float x) {
    float s = 1.f / (1.f + __expf(-2.f * x));
    return 2.f * s - 1.f;
}
__device__ __forceinline__ uint32_t smem_u32(const void* p) {
    uint32_t a;
    asm("{ .reg .u64 t; cvta.to.shared.u64 t, %1; cvt.u32.u64 %0, t; }" : "=r"(a) : "l"(p));
    return a;
}
__device__ __forceinline__ float ldcs(const float* p) {
    float v; asm volatile("ld.global.cs.f32 %0, [%1];" : "=f"(v) : "l"(p)); return v;
}
__device__ __forceinline__ void stcs(float* p, float v) {
    asm volatile("st.global.cs.f32 [%0], %1;" :: "l"(p), "f"(v));
}

// ---------------- device scratch ----------------
__device__ __align__(16) __nv_bfloat16 g_abf[(size_t)NNODES * KP];    // A' = [hi|lo|hi]
__device__ __align__(16) __nv_bfloat16 g_bbf[2][(size_t)NP * KP];     // B' = [hi|hi|lo]
__device__ __align__(16) __nv_bfloat16 g_gwr[(size_t)2 * RKC * RROWS * 16]; // W_hh chunks
__device__ float g_xg[2][(size_t)NNODES * G];
__device__ float g_h0[NB * H];
__device__ int   g_sstart[NB];
__device__ int   g_slen[NB];

// ---------------- 1) segment bounds ----------------
__global__ void k_seg(const int* __restrict__ batch, const int* __restrict__ pos, int n) {
    int i = blockIdx.x * blockDim.x + threadIdx.x;
    if (i >= n) return;
    int b = batch[i];
    if (pos[i] == 0) g_sstart[b] = i;
    if (i == n - 1 || batch[i + 1] != b) g_slen[b] = pos[i] + 1;
}

// ---------------- 2) h0 = per-graph segment max ----------------
__global__ void __launch_bounds__(NTHREADS) k_h0(const float* __restrict__ node) {
    int b = blockIdx.x, h = threadIdx.x;
    if (h >= H) return;
    int s = g_sstart[b], l = g_slen[b];
    float m = -3.402823466e38f;
    for (int i = 0; i < l; ++i) m = fmaxf(m, node[(size_t)(s + i) * H + h]);
    g_h0[b * H + h] = m;
}

// ---------------- 3) A' = split-bf16 of relu(node + bias) ----------------
__global__ void k_convA(const float* __restrict__ node, const float* __restrict__ bias, int n) {
    size_t tot = (size_t)n * KP;
    for (size_t idx = (size_t)blockIdx.x * blockDim.x + threadIdx.x; idx < tot;
         idx += (size_t)gridDim.x * blockDim.x) {
        size_t i = idx / KP;
        int kp = (int)(idx - i * KP);
        __nv_bfloat16 o = __float2bfloat16(0.f);
        int k = -1; bool lo = false;
        if (kp < 300)                    { k = kp; }
        else if (kp >= 320 && kp < 620)  { k = kp - 320; lo = true; }
        else if (kp >= 640 && kp < 940)  { k = kp - 640; }
        if (k >= 0) {
            float m = node[i * H + k] + bias[k];
            m = m > 0.f ? m : 0.f;
            __nv_bfloat16 hi = __float2bfloat16(m);
            o = lo ? __float2bfloat16(m - __bfloat162float(hi)) : hi;
        }
        g_abf[idx] = o;
    }
}

// ---------------- 4) B' = split-bf16 of w_ih ----------------
__global__ void k_convB(const float* __restrict__ wif, const float* __restrict__ wib) {
    size_t tot = (size_t)2 * NP * KP;
    for (size_t idx = (size_t)blockIdx.x * blockDim.x + threadIdx.x; idx < tot;
         idx += (size_t)gridDim.x * blockDim.x) {
        int dir = (int)(idx / ((size_t)NP * KP));
        size_t r = idx - (size_t)dir * NP * KP;
        int g = (int)(r / KP), kp = (int)(r - (size_t)g * KP);
        __nv_bfloat16 o = __float2bfloat16(0.f);
        int k = -1; bool lo = false;
        if (kp < 300)                    { k = kp; }
        else if (kp >= 320 && kp < 620)  { k = kp - 320; }
        else if (kp >= 640 && kp < 940)  { k = kp - 640; lo = true; }
        if (k >= 0 && g < G) {
            const float* w = dir ? wib : wif;
            float v = w[(size_t)g * H + k];
            __nv_bfloat16 hi = __float2bfloat16(v);
            o = lo ? __float2bfloat16(v - __bfloat162float(hi)) : hi;
        }
        g_bbf[dir][r] = o;
    }
}

// ---------------- 5) W_hh -> chunked split layout [dir][kc][row 0..959][16] ----------------
// kc<19: W_hi at k=kc*16+c; kc>=19: W_lo at k=(kc-19)*16+c. row = gate*GP + j.
__global__ void k_convW(const float* __restrict__ whf, const float* __restrict__ whb) {
    const int tot = 2 * RKC * RROWS * 16;
    for (int idx = blockIdx.x * blockDim.x + threadIdx.x; idx < tot;
         idx += gridDim.x * blockDim.x) {
        int dir = idx / (RKC * RROWS * 16);
        int r = idx % (RKC * RROWS * 16);
        int kc = r / (RROWS * 16);
        int rr = r % (RROWS * 16);
        int row = rr >> 4, c = rr & 15;
        int gate = row / GP, j = row % GP;
        bool lo = kc >= 19;
        int k = (lo ? kc - 19 : kc) * 16 + c;
        __nv_bfloat16 o = __float2bfloat16(0.f);
        if (j < H && k < H) {
            const float* w = dir ? whb : whf;
            float v = w[(size_t)(gate * H + j) * H + k];
            __nv_bfloat16 hi = __float2bfloat16(v);
            o = lo ? __float2bfloat16(v - __bfloat162float(hi)) : hi;
        }
        g_gwr[idx] = o;
    }
}

// ---------------- 6) input GEMM via mma.sync (proven round-4) ----------------
__global__ void __launch_bounds__(256, 2) k_gemm_mma(const float* __restrict__ bih_f,
                                                     const float* __restrict__ bih_b) {
    __shared__ __align__(16) unsigned char sA[2][MT * SROW];
    __shared__ __align__(16) unsigned char sB[2][128 * SROW];
    const int tid = threadIdx.x, lane = tid & 31, wid = tid >> 5;
    const int dir = blockIdx.x >> 3, ntile = blockIdx.x & 7;
    const int m0 = blockIdx.y * MT, n0 = ntile * 128;
    const int wm = wid & 3, wn = wid >> 2;

    const __nv_bfloat16* __restrict__ A = g_abf + (size_t)m0 * KP;
    const __nv_bfloat16* __restrict__ B = g_bbf[dir] + (size_t)n0 * KP;
    const uint32_t sA0 = smem_u32(sA), sB0 = smem_u32(sB);

    float d[2][8][4];
#pragma unroll
    for (int mi = 0; mi < 2; ++mi)
#pragma unroll
        for (int ni = 0; ni < 8; ++ni)
#pragma unroll
            for (int e = 0; e < 4; ++e) d[mi][ni][e] = 0.f;

#define ISSUE_STAGE(kb) do {                                                        \
    int _buf = (kb) & 1;                                                            \
    _Pragma("unroll")                                                               \
    for (int _p = 0; _p < 2; ++_p) {                                                \
        int _u = _p * 256 + tid, _row = _u >> 2, _c = _u & 3;                       \
        const void* _ga = A + (size_t)_row * KP + (kb) * 32 + _c * 8;               \
        uint32_t _da = sA0 + _buf * (MT * SROW) + _row * SROW + _c * 16;            \
        asm volatile("cp.async.cg.shared.global [%0], [%1], 16;" :: "r"(_da), "l"(_ga)); \
        const void* _gb = B + (size_t)_row * KP + (kb) * 32 + _c * 8;               \
        uint32_t _db = sB0 + _buf * (128 * SROW) + _row * SROW + _c * 16;           \
        asm volatile("cp.async.cg.shared.global [%0], [%1], 16;" :: "r"(_db), "l"(_gb)); \
    }                                                                               \
    asm volatile("cp.async.commit_group;" ::: "memory");                            \
} while (0)

    ISSUE_STAGE(0);
    for (int kb = 0; kb < NKB2; ++kb) {
        if (kb + 1 < NKB2) {
            ISSUE_STAGE(kb + 1);
            asm volatile("cp.async.wait_group 1;" ::: "memory");
        } else {
            asm volatile("cp.async.wait_group 0;" ::: "memory");
        }
        __syncthreads();
        const uint32_t* a32 = (const uint32_t*)(sA[kb & 1]);
        const uint32_t* b32 = (const uint32_t*)(sB[kb & 1]);
#pragma unroll
        for (int ks = 0; ks < 2; ++ks) {
            uint32_t af[2][4];
#pragma unroll
            for (int mi = 0; mi < 2; ++mi) {
                int r0 = wm * 32 + mi * 16 + (lane >> 2);
                af[mi][0] = a32[r0 * 20 + ks * 8 + (lane & 3)];
                af[mi][1] = a32[(r0 + 8) * 20 + ks * 8 + (lane & 3)];
                af[mi][2] = a32[r0 * 20 + ks * 8 + 4 + (lane & 3)];
                af[mi][3] = a32[(r0 + 8) * 20 + ks * 8 + 4 + (lane & 3)];
            }
#pragma unroll
            for (int ni = 0; ni < 8; ++ni) {
                int cn = wn * 64 + ni * 8 + (lane >> 2);
                uint32_t b0 = b32[cn * 20 + ks * 8 + (lane & 3)];
                uint32_t b1 = b32[cn * 20 + ks * 8 + 4 + (lane & 3)];
#pragma unroll
                for (int mi = 0; mi < 2; ++mi) {
                    asm volatile(
                        "mma.sync.aligned.m16n8k16.row.col.f32.bf16.bf16.f32 "
                        "{%0,%1,%2,%3}, {%4,%5,%6,%7}, {%8,%9}, {%0,%1,%2,%3};"
                        : "+f"(d[mi][ni][0]), "+f"(d[mi][ni][1]),
                          "+f"(d[mi][ni][2]), "+f"(d[mi][ni][3])
                        : "r"(af[mi][0]), "r"(af[mi][1]), "r"(af[mi][2]), "r"(af[mi][3]),
                          "r"(b0), "r"(b1));
                }
            }
        }
        __syncthreads();
    }
#undef ISSUE_STAGE

    const float* __restrict__ bih = dir ? bih_b : bih_f;
    float* __restrict__ xg = g_xg[dir];
#pragma unroll
    for (int mi = 0; mi < 2; ++mi) {
        int r0 = m0 + wm * 32 + mi * 16 + (lane >> 2);
#pragma unroll
        for (int ni = 0; ni < 8; ++ni) {
            int g = n0 + wn * 64 + ni * 8 + (lane & 3) * 2;
            if (g < G) {
                float bg0 = bih[g], bg1 = bih[g + 1];
                *(float2*)(xg + (size_t)r0 * G + g) =
                    make_float2(d[mi][ni][0] + bg0, d[mi][ni][1] + bg1);
                *(float2*)(xg + (size_t)(r0 + 8) * G + g) =
                    make_float2(d[mi][ni][2] + bg0, d[mi][ni][3] + bg1);
            }
        }
    }
}

// ---------------- 7) recurrent GRU via mma.sync, per-warp streamed weights ----------------
__global__ void __launch_bounds__(RNT, 1) k_recur_mma(const float* __restrict__ bih_f,
                                                      const float* __restrict__ bih_b,
                                                      const float* __restrict__ bhh_f,
                                                      const float* __restrict__ bhh_b,
                                                      float* __restrict__ out) {
    extern __shared__ char smem[];
    float*           Dsm  = (float*)(smem + SM_D);
    uint32_t*        hs32 = (uint32_t*)(smem + SM_HS);
    __nv_bfloat16*   hsb  = (__nv_bfloat16*)(smem + SM_HS);
    float*           hf   = (float*)(smem + SM_HF);
    float*           sbhh = (float*)(smem + SM_BH);
    float*           sbih = (float*)(smem + SM_BI);
    int*             sst  = (int*)(smem + SM_MISC);
    int*             sln  = sst + RBT;

    const int tid = threadIdx.x, lane = tid & 31, wid = tid >> 5;
    const int dir = blockIdx.y;
    const int b0 = blockIdx.x * RBT;
    const int wrow0 = wid * 80;                         // this warp's 5 m16-tiles
    const uint32_t swb = smem_u32(smem);
    const int sw = (lane & 16) ? 4 : 0;                 // lane-constant A-frag swizzle

    const __nv_bfloat16* __restrict__ gw = g_gwr + (size_t)dir * RKC * RROWS * 16;
    const float* __restrict__ xg = g_xg[dir];

    // ---- per-warp chunk issue: 80 rows x 32B, 16B-granule swizzle on row bit2 ----
#define ISSUE_WCHUNK(pfc, stg) do {                                                 \
    const char* _src = (const char*)(gw + (size_t)(pfc) * (RROWS * 16)) + wrow0 * 32; \
    _Pragma("unroll")                                                               \
    for (int _i = 0; _i < 5; ++_i) {                                                \
        int _fl = lane + 32 * _i;                                                   \
        int _row = _fl >> 1, _half = _fl & 1;                                       \
        int _ar = wrow0 + _row;                                                     \
        int _hsw = _half ^ ((_ar >> 2) & 1);                                        \
        uint32_t _d = swb + (stg) * WSTG + _ar * 32 + (_hsw << 4);                  \
        const void* _s = _src + _row * 32 + _half * 16;                             \
        asm volatile("cp.async.cg.shared.global [%0], [%1], 16;" :: "r"(_d), "l"(_s)); \
    }                                                                               \
    asm volatile("cp.async.commit_group;" ::: "memory");                            \
} while (0)

    // preload chunks 0..3 into stages 0..3 (per-warp, 4 groups outstanding)
#pragma unroll
    for (int p = 0; p < 4; ++p) ISSUE_WCHUNK(p, p);

    // ---- init shared state ----
    if (tid < RBT) { sst[tid] = g_sstart[b0 + tid]; sln[tid] = g_slen[b0 + tid]; }
    for (int i = tid; i < RBT * (HSS / 2); i += RNT) hs32[i] = 0u;
    {
        const float* bhh = dir ? bhh_b : bhh_f;
        const float* bih = dir ? bih_b : bih_f;
        for (int i = tid; i < G; i += RNT) { sbhh[i] = bhh[i]; sbih[i] = bih[i]; }
    }
    __syncthreads();
    for (int it = tid; it < RBT * H; it += RNT) {
        int j = it >> 4, b = it & 15;
        float v = g_h0[(b0 + b) * H + j];
        hf[b * HFS + j] = v;
        __nv_bfloat16 hi = __float2bfloat16(v);
        hsb[b * HSS + j] = hi;
        hsb[b * HSS + 320 + j] = __float2bfloat16(v - __bfloat162float(hi));
    }
    __syncthreads();

    for (int s = 0; s < LSEQ; ++s) {
        int t = dir ? (LSEQ - 1 - s) : s;
        float acc[5][2][4];
#pragma unroll
        for (int i = 0; i < 5; ++i)
#pragma unroll
            for (int nt = 0; nt < 2; ++nt)
#pragma unroll
                for (int e = 0; e < 4; ++e) acc[i][nt][e] = 0.f;

        const int sbase = 2 * (s & 1);                  // (38*s) mod 4
#pragma unroll 1
        for (int kc = 0; kc < RKC; ++kc) {
            const int stage = (kc + sbase) & 3;
            asm volatile("cp.async.wait_group 3;" ::: "memory");  // chunk kc landed
            const uint32_t* w32 = (const uint32_t*)(smem + (size_t)stage * WSTG);
            const int npass = (kc < 19) ? 2 : 1;
            const int hk0 = (kc < 19) ? kc * 8 : (kc - 19) * 8;
#pragma unroll 1
            for (int pass = 0; pass < npass; ++pass) {
                const int hk = pass ? (160 + kc * 8) : hk0;
                uint32_t bfr[2][2];
#pragma unroll
                for (int nt = 0; nt < 2; ++nt) {
                    int nr = nt * 8 + (lane >> 2);
                    bfr[nt][0] = hs32[nr * (HSS / 2) + hk + (lane & 3)];
                    bfr[nt][1] = hs32[nr * (HSS / 2) + hk + 4 + (lane & 3)];
                }
#pragma unroll
                for (int i = 0; i < 5; ++i) {
                    int r0 = wrow0 + i * 16 + (lane >> 2);
                    int base = r0 * 8;
                    int c0 = (lane & 3) ^ sw, c2 = (4 + (lane & 3)) ^ sw;
                    uint32_t a0 = w32[base + c0];
                    uint32_t a1 = w32[base + 64 + c0];
                    uint32_t a2 = w32[base + c2];
                    uint32_t a3 = w32[base + 64 + c2];
#pragma unroll
                    for (int nt = 0; nt < 2; ++nt) {
                        asm volatile(
                            "mma.sync.aligned.m16n8k16.row.col.f32.bf16.bf16.f32 "
                            "{%0,%1,%2,%3}, {%4,%5,%6,%7}, {%8,%9}, {%0,%1,%2,%3};"
                            : "+f"(acc[i][nt][0]), "+f"(acc[i][nt][1]),
                              "+f"(acc[i][nt][2]), "+f"(acc[i][nt][3])
                            : "r"(a0), "r"(a1), "r"(a2), "r"(a3),
                              "r"(bfr[nt][0]), "r"(bfr[nt][1]));
                    }
                }
            }
            // prefetch chunk kc+4 (wraps to next step's weights) into just-freed stage;
            // safe: MMAs above issued only after their LDS completed (in-order issue)
            int pfc = kc + 4; if (pfc >= RKC) pfc -= RKC;
            ISSUE_WCHUNK(pfc, stage);
        }

        // write hg preactivations D[row][graph]
#pragma unroll
        for (int i = 0; i < 5; ++i) {
            int r0 = wrow0 + i * 16 + (lane >> 2);
#pragma unroll
            for (int nt = 0; nt < 2; ++nt) {
                int c = nt * 8 + (lane & 3) * 2;
                *(float2*)(Dsm + r0 * 16 + c) = make_float2(acc[i][nt][0], acc[i][nt][1]);
                *(float2*)(Dsm + (r0 + 8) * 16 + c) = make_float2(acc[i][nt][2], acc[i][nt][3]);
            }
        }
        __syncthreads();

        // pointwise GRU update
        for (int it = tid; it < RBT * H; it += RNT) {
            int j = it >> 4, b = it & 15;
            bool valid = t < sln[b];
            size_t ni = (size_t)(sst[b] + t);
            float x0, x1, x2;
            if (valid) {
                const float* xr = xg + ni * G;
                x0 = ldcs(xr + j); x1 = ldcs(xr + H + j); x2 = ldcs(xr + 2 * H + j);
            } else {
                x0 = sbih[j]; x1 = sbih[H + j]; x2 = sbih[2 * H + j];
            }
            float hgr = Dsm[j * 16 + b];
            float hgz = Dsm[(GP + j) * 16 + b];
            float hgn = Dsm[(2 * GP + j) * 16 + b];
            float r  = sigm(x0 + hgr + sbhh[j]);
            float z  = sigm(x1 + hgz + sbhh[H + j]);
            float nn = tanh_fast(x2 + r * (hgn + sbhh[2 * H + j]));
            float hp = hf[b * HFS + j];
            float hv = (1.f - z) * nn + z * hp;
            hf[b * HFS + j] = hv;
            __nv_bfloat16 hi = __float2bfloat16(hv);
            hsb[b * HSS + j] = hi;
            hsb[b * HSS + 320 + j] = __float2bfloat16(hv - __bfloat162float(hi));
            if (valid) stcs(out + ni * (2 * H) + dir * H + j, hv);
        }
        __syncthreads();
    }
    asm volatile("cp.async.wait_group 0;" ::: "memory");   // drain before exit
#undef ISSUE_WCHUNK
}

// ---------------- host entry ----------------
extern "C" void kernel_launch(void* const* d_in, const int* in_sizes, int n_in,
                              void* d_out, int out_size) {
    const float* node   = (const float*)d_in[0];
    const int*   batch  = (const int*)d_in[1];
    const int*   pos    = (const int*)d_in[2];
    const float* bias   = (const float*)d_in[3];
    const float* w_ih_f = (const float*)d_in[4];
    const float* w_hh_f = (const float*)d_in[5];
    const float* b_ih_f = (const float*)d_in[6];
    const float* b_hh_f = (const float*)d_in[7];
    const float* w_ih_b = (const float*)d_in[8];
    const float* w_hh_b = (const float*)d_in[9];
    const float* b_ih_b = (const float*)d_in[10];
    const float* b_hh_b = (const float*)d_in[11];
    float* out = (float*)d_out;
    int n = in_sizes[0] / H;

    cudaFuncSetAttribute(k_recur_mma, cudaFuncAttributeMaxDynamicSharedMemorySize, SM_TOT);

    k_seg<<<(n + 255) / 256, 256>>>(batch, pos, n);
    k_h0<<<NB, NTHREADS>>>(node);
    k_convA<<<4096, 256>>>(node, bias, n);
    k_convB<<<2048, 256>>>(w_ih_f, w_ih_b);
    k_convW<<<1024, 256>>>(w_hh_f, w_hh_b);
    k_gemm_mma<<<dim3(16, n / MT), 256>>>(b_ih_f, b_ih_b);
    k_recur_mma<<<dim3(NB / RBT, 2), RNT, SM_TOT>>>(b_ih_f, b_ih_b, b_hh_f, b_hh_b, out);
}

// round 7
// speedup vs baseline: 2.0552x; 1.0761x over previous
#include <cuda_runtime.h>
#include <cuda_bf16.h>
#include <math.h>
#include <cstdint>

#define H     300
#define G     900
#define NB    1024
#define LSEQ  64
#define NTHREADS 320
#define NNODES 49152

// ---- input GEMM config (proven round-4 path) ----
#define KP  960
#define NP  1024
#define MT  128
#define NKB2 (KP / 32)
#define SROW 80

// ---- recurrent mma config ----
#define GP    320                  // padded rows per gate (20 m16-tiles)
#define RROWS 960                  // 3*GP
#define RKC   38                   // k16 chunks: 19 (W_hi) + 19 (W_lo)
#define WSTG  (RROWS * 32)         // one stage: 960 rows x 32B = 30720
#define HSS   648                  // h-split smem row stride (bf16)
#define HFS   304                  // h fp32 smem row stride
#define RBT   16                   // graphs per CTA
#define RNT   384                  // 12 warps

// dynamic smem layout for k_recur_mma (bytes)
#define SM_W    0
#define SM_D    (4 * WSTG)                    // 122880
#define SM_HS   (SM_D + RROWS * 16 * 4)       // 184320
#define SM_HF   (SM_HS + RBT * HSS * 2)       // 205056
#define SM_BH   (SM_HF + RBT * HFS * 4)       // 224512
#define SM_BI   (SM_BH + 3600)                // 228112
#define SM_MISC (SM_BI + 3600)                // 231712
#define SM_TOT  (SM_MISC + 128)               // 231840 (<= 232448 opt-in)

__device__ __forceinline__ float sigm(float x) { return 1.f / (1.f + __expf(-x)); }
__device__ __forceinline__ float tanh_fast(float x) {
    float s = 1.f / (1.f + __expf(-2.f * x));
    return 2.f * s - 1.f;
}
__device__ __forceinline__ uint32_t smem_u32(const void* p) {
    uint32_t a;
    asm("{ .reg .u64 t; cvta.to.shared.u64 t, %1; cvt.u32.u64 %0, t; }" : "=r"(a) : "l"(p));
    return a;
}
__device__ __forceinline__ float ldcs(const float* p) {
    float v; asm volatile("ld.global.cs.f32 %0, [%1];" : "=f"(v) : "l"(p)); return v;
}
__device__ __forceinline__ void stcs(float* p, float v) {
    asm volatile("st.global.cs.f32 [%0], %1;" :: "l"(p), "f"(v));
}

// ---------------- device scratch ----------------
__device__ __align__(16) __nv_bfloat16 g_abf[(size_t)NNODES * KP];    // A' = [hi|lo|hi]
__device__ __align__(16) __nv_bfloat16 g_bbf[2][(size_t)NP * KP];     // B' = [hi|hi|lo]
__device__ __align__(16) __nv_bfloat16 g_gwr[(size_t)2 * RKC * RROWS * 16]; // W_hh chunks
__device__ float g_xg[2][(size_t)NNODES * G];
__device__ float g_h0[NB * H];
__device__ int   g_sstart[NB];
__device__ int   g_slen[NB];

// ---------------- 1) segment bounds ----------------
__global__ void k_seg(const int* __restrict__ batch, const int* __restrict__ pos, int n) {
    int i = blockIdx.x * blockDim.x + threadIdx.x;
    if (i >= n) return;
    int b = batch[i];
    if (pos[i] == 0) g_sstart[b] = i;
    if (i == n - 1 || batch[i + 1] != b) g_slen[b] = pos[i] + 1;
}

// ---------------- 2) h0 = per-graph segment max ----------------
__global__ void __launch_bounds__(NTHREADS) k_h0(const float* __restrict__ node) {
    int b = blockIdx.x, h = threadIdx.x;
    if (h >= H) return;
    int s = g_sstart[b], l = g_slen[b];
    float m = -3.402823466e38f;
    for (int i = 0; i < l; ++i) m = fmaxf(m, node[(size_t)(s + i) * H + h]);
    g_h0[b * H + h] = m;
}

// ---------------- 3) A' = split-bf16 of relu(node + bias): one block per node ----------------
__global__ void __launch_bounds__(256) k_convA(const float* __restrict__ node,
                                               const float* __restrict__ bias, int n) {
    __shared__ float sb[H];
    int i = blockIdx.x;
    int tid = threadIdx.x;
    for (int k = tid; k < H; k += 256) {
        float v = node[(size_t)i * H + k] + bias[k];
        sb[k] = v > 0.f ? v : 0.f;
    }
    __syncthreads();
    __nv_bfloat16* dst = g_abf + (size_t)i * KP;
    for (int kp = tid; kp < KP; kp += 256) {
        __nv_bfloat16 o = __float2bfloat16(0.f);
        int k = -1; bool lo = false;
        if (kp < 300)                    { k = kp; }
        else if (kp >= 320 && kp < 620)  { k = kp - 320; lo = true; }
        else if (kp >= 640 && kp < 940)  { k = kp - 640; }
        if (k >= 0) {
            float m = sb[k];
            __nv_bfloat16 hi = __float2bfloat16(m);
            o = lo ? __float2bfloat16(m - __bfloat162float(hi)) : hi;
        }
        dst[kp] = o;
    }
}

// ---------------- 4) B' = split-bf16 of w_ih ----------------
__global__ void k_convB(const float* __restrict__ wif, const float* __restrict__ wib) {
    size_t tot = (size_t)2 * NP * KP;
    for (size_t idx = (size_t)blockIdx.x * blockDim.x + threadIdx.x; idx < tot;
         idx += (size_t)gridDim.x * blockDim.x) {
        int dir = (int)(idx / ((size_t)NP * KP));
        size_t r = idx - (size_t)dir * NP * KP;
        int g = (int)(r / KP), kp = (int)(r - (size_t)g * KP);
        __nv_bfloat16 o = __float2bfloat16(0.f);
        int k = -1; bool lo = false;
        if (kp < 300)                    { k = kp; }
        else if (kp >= 320 && kp < 620)  { k = kp - 320; }
        else if (kp >= 640 && kp < 940)  { k = kp - 640; lo = true; }
        if (k >= 0 && g < G) {
            const float* w = dir ? wib : wif;
            float v = w[(size_t)g * H + k];
            __nv_bfloat16 hi = __float2bfloat16(v);
            o = lo ? __float2bfloat16(v - __bfloat162float(hi)) : hi;
        }
        g_bbf[dir][r] = o;
    }
}

// ---------------- 5) W_hh -> chunked split layout [dir][kc][row 0..959][16] ----------------
__global__ void k_convW(const float* __restrict__ whf, const float* __restrict__ whb) {
    const int tot = 2 * RKC * RROWS * 16;
    for (int idx = blockIdx.x * blockDim.x + threadIdx.x; idx < tot;
         idx += gridDim.x * blockDim.x) {
        int dir = idx / (RKC * RROWS * 16);
        int r = idx % (RKC * RROWS * 16);
        int kc = r / (RROWS * 16);
        int rr = r % (RROWS * 16);
        int row = rr >> 4, c = rr & 15;
        int gate = row / GP, j = row % GP;
        bool lo = kc >= 19;
        int k = (lo ? kc - 19 : kc) * 16 + c;
        __nv_bfloat16 o = __float2bfloat16(0.f);
        if (j < H && k < H) {
            const float* w = dir ? whb : whf;
            float v = w[(size_t)(gate * H + j) * H + k];
            __nv_bfloat16 hi = __float2bfloat16(v);
            o = lo ? __float2bfloat16(v - __bfloat162float(hi)) : hi;
        }
        g_gwr[idx] = o;
    }
}

// ---------------- 6) input GEMM via mma.sync (proven round-4) ----------------
__global__ void __launch_bounds__(256, 2) k_gemm_mma(const float* __restrict__ bih_f,
                                                     const float* __restrict__ bih_b) {
    __shared__ __align__(16) unsigned char sA[2][MT * SROW];
    __shared__ __align__(16) unsigned char sB[2][128 * SROW];
    const int tid = threadIdx.x, lane = tid & 31, wid = tid >> 5;
    const int dir = blockIdx.x >> 3, ntile = blockIdx.x & 7;
    const int m0 = blockIdx.y * MT, n0 = ntile * 128;
    const int wm = wid & 3, wn = wid >> 2;

    const __nv_bfloat16* __restrict__ A = g_abf + (size_t)m0 * KP;
    const __nv_bfloat16* __restrict__ B = g_bbf[dir] + (size_t)n0 * KP;
    const uint32_t sA0 = smem_u32(sA), sB0 = smem_u32(sB);

    float d[2][8][4];
#pragma unroll
    for (int mi = 0; mi < 2; ++mi)
#pragma unroll
        for (int ni = 0; ni < 8; ++ni)
#pragma unroll
            for (int e = 0; e < 4; ++e) d[mi][ni][e] = 0.f;

#define ISSUE_STAGE(kb) do {                                                        \
    int _buf = (kb) & 1;                                                            \
    _Pragma("unroll")                                                               \
    for (int _p = 0; _p < 2; ++_p) {                                                \
        int _u = _p * 256 + tid, _row = _u >> 2, _c = _u & 3;                       \
        const void* _ga = A + (size_t)_row * KP + (kb) * 32 + _c * 8;               \
        uint32_t _da = sA0 + _buf * (MT * SROW) + _row * SROW + _c * 16;            \
        asm volatile("cp.async.cg.shared.global [%0], [%1], 16;" :: "r"(_da), "l"(_ga)); \
        const void* _gb = B + (size_t)_row * KP + (kb) * 32 + _c * 8;               \
        uint32_t _db = sB0 + _buf * (128 * SROW) + _row * SROW + _c * 16;           \
        asm volatile("cp.async.cg.shared.global [%0], [%1], 16;" :: "r"(_db), "l"(_gb)); \
    }                                                                               \
    asm volatile("cp.async.commit_group;" ::: "memory");                            \
} while (0)

    ISSUE_STAGE(0);
    for (int kb = 0; kb < NKB2; ++kb) {
        if (kb + 1 < NKB2) {
            ISSUE_STAGE(kb + 1);
            asm volatile("cp.async.wait_group 1;" ::: "memory");
        } else {
            asm volatile("cp.async.wait_group 0;" ::: "memory");
        }
        __syncthreads();
        const uint32_t* a32 = (const uint32_t*)(sA[kb & 1]);
        const uint32_t* b32 = (const uint32_t*)(sB[kb & 1]);
#pragma unroll
        for (int ks = 0; ks < 2; ++ks) {
            uint32_t af[2][4];
#pragma unroll
            for (int mi = 0; mi < 2; ++mi) {
                int r0 = wm * 32 + mi * 16 + (lane >> 2);
                af[mi][0] = a32[r0 * 20 + ks * 8 + (lane & 3)];
                af[mi][1] = a32[(r0 + 8) * 20 + ks * 8 + (lane & 3)];
                af[mi][2] = a32[r0 * 20 + ks * 8 + 4 + (lane & 3)];
                af[mi][3] = a32[(r0 + 8) * 20 + ks * 8 + 4 + (lane & 3)];
            }
#pragma unroll
            for (int ni = 0; ni < 8; ++ni) {
                int cn = wn * 64 + ni * 8 + (lane >> 2);
                uint32_t b0 = b32[cn * 20 + ks * 8 + (lane & 3)];
                uint32_t b1 = b32[cn * 20 + ks * 8 + 4 + (lane & 3)];
#pragma unroll
                for (int mi = 0; mi < 2; ++mi) {
                    asm volatile(
                        "mma.sync.aligned.m16n8k16.row.col.f32.bf16.bf16.f32 "
                        "{%0,%1,%2,%3}, {%4,%5,%6,%7}, {%8,%9}, {%0,%1,%2,%3};"
                        : "+f"(d[mi][ni][0]), "+f"(d[mi][ni][1]),
                          "+f"(d[mi][ni][2]), "+f"(d[mi][ni][3])
                        : "r"(af[mi][0]), "r"(af[mi][1]), "r"(af[mi][2]), "r"(af[mi][3]),
                          "r"(b0), "r"(b1));
                }
            }
        }
        __syncthreads();
    }
#undef ISSUE_STAGE

    const float* __restrict__ bih = dir ? bih_b : bih_f;
    float* __restrict__ xg = g_xg[dir];
#pragma unroll
    for (int mi = 0; mi < 2; ++mi) {
        int r0 = m0 + wm * 32 + mi * 16 + (lane >> 2);
#pragma unroll
        for (int ni = 0; ni < 8; ++ni) {
            int g = n0 + wn * 64 + ni * 8 + (lane & 3) * 2;
            if (g < G) {
                float bg0 = bih[g], bg1 = bih[g + 1];
                *(float2*)(xg + (size_t)r0 * G + g) =
                    make_float2(d[mi][ni][0] + bg0, d[mi][ni][1] + bg1);
                *(float2*)(xg + (size_t)(r0 + 8) * G + g) =
                    make_float2(d[mi][ni][2] + bg0, d[mi][ni][3] + bg1);
            }
        }
    }
}

// ---------------- 7) recurrent GRU via mma.sync, fused passes + ldmatrix ----------------
__global__ void __launch_bounds__(RNT, 1) k_recur_mma(const float* __restrict__ bih_f,
                                                      const float* __restrict__ bih_b,
                                                      const float* __restrict__ bhh_f,
                                                      const float* __restrict__ bhh_b,
                                                      float* __restrict__ out) {
    extern __shared__ char smem[];
    float*           Dsm  = (float*)(smem + SM_D);
    uint32_t*        hs32 = (uint32_t*)(smem + SM_HS);
    __nv_bfloat16*   hsb  = (__nv_bfloat16*)(smem + SM_HS);
    float*           hf   = (float*)(smem + SM_HF);
    float*           sbhh = (float*)(smem + SM_BH);
    float*           sbih = (float*)(smem + SM_BI);
    int*             sst  = (int*)(smem + SM_MISC);
    int*             sln  = sst + RBT;

    const int tid = threadIdx.x, lane = tid & 31, wid = tid >> 5;
    const int dir = blockIdx.y;
    const int b0 = blockIdx.x * RBT;
    const int wrow0 = wid * 80;                         // this warp's 5 m16-tiles
    const uint32_t swb = smem_u32(smem);

    // per-lane ldmatrix row offsets for the 5 A-tiles (swizzle baked in)
    uint32_t afro[5];
    {
        int lsel = lane >> 3, lrow = lane & 7;
        int half = lsel >> 1;
#pragma unroll
        for (int i = 0; i < 5; ++i) {
            int row = wrow0 + i * 16 + lrow + ((lsel & 1) << 3);
            afro[i] = row * 32 + ((half ^ ((row >> 2) & 1)) << 4);
        }
    }

    const __nv_bfloat16* __restrict__ gw = g_gwr + (size_t)dir * RKC * RROWS * 16;
    const float* __restrict__ xg = g_xg[dir];

    // ---- per-warp chunk issue: 80 rows x 32B, 16B-granule swizzle on row bit2 ----
#define ISSUE_WCHUNK(pfc, stg) do {                                                 \
    const char* _src = (const char*)(gw + (size_t)(pfc) * (RROWS * 16)) + wrow0 * 32; \
    _Pragma("unroll")                                                               \
    for (int _i = 0; _i < 5; ++_i) {                                                \
        int _fl = lane + 32 * _i;                                                   \
        int _row = _fl >> 1, _half = _fl & 1;                                       \
        int _ar = wrow0 + _row;                                                     \
        int _hsw = _half ^ ((_ar >> 2) & 1);                                        \
        uint32_t _d = swb + (stg) * WSTG + _ar * 32 + (_hsw << 4);                  \
        const void* _s = _src + _row * 32 + _half * 16;                             \
        asm volatile("cp.async.cg.shared.global [%0], [%1], 16;" :: "r"(_d), "l"(_s)); \
    }                                                                               \
    asm volatile("cp.async.commit_group;" ::: "memory");                            \
} while (0)

#pragma unroll
    for (int p = 0; p < 4; ++p) ISSUE_WCHUNK(p, p);

    // ---- init shared state ----
    if (tid < RBT) { sst[tid] = g_sstart[b0 + tid]; sln[tid] = g_slen[b0 + tid]; }
    for (int i = tid; i < RBT * (HSS / 2); i += RNT) hs32[i] = 0u;
    {
        const float* bhh = dir ? bhh_b : bhh_f;
        const float* bih = dir ? bih_b : bih_f;
        for (int i = tid; i < G; i += RNT) { sbhh[i] = bhh[i]; sbih[i] = bih[i]; }
    }
    __syncthreads();
    for (int it = tid; it < RBT * H; it += RNT) {
        int j = it >> 4, b = it & 15;
        float v = g_h0[(b0 + b) * H + j];
        hf[b * HFS + j] = v;
        __nv_bfloat16 hi = __float2bfloat16(v);
        hsb[b * HSS + j] = hi;
        hsb[b * HSS + 320 + j] = __float2bfloat16(v - __bfloat162float(hi));
    }
    __syncthreads();

    for (int s = 0; s < LSEQ; ++s) {
        int t = dir ? (LSEQ - 1 - s) : s;
        float acc[5][2][4];
#pragma unroll
        for (int i = 0; i < 5; ++i)
#pragma unroll
            for (int nt = 0; nt < 2; ++nt)
#pragma unroll
                for (int e = 0; e < 4; ++e) acc[i][nt][e] = 0.f;

        const int sbase = 2 * (s & 1);                  // (38*s) mod 4
#pragma unroll 1
        for (int kc = 0; kc < RKC; ++kc) {
            const int stage = (kc + sbase) & 3;
            asm volatile("cp.async.wait_group 3;" ::: "memory");  // chunk kc landed
            const uint32_t wbase = swb + (uint32_t)stage * WSTG;
            const bool hi = (kc < 19);
            const int hk = (hi ? kc : kc - 19) * 8;

            // A fragments once per chunk via ldmatrix.x4
            uint32_t A[5][4];
#pragma unroll
            for (int i = 0; i < 5; ++i) {
                asm volatile("ldmatrix.sync.aligned.m8n8.x4.shared.b16 "
                             "{%0,%1,%2,%3}, [%4];"
                             : "=r"(A[i][0]), "=r"(A[i][1]), "=r"(A[i][2]), "=r"(A[i][3])
                             : "r"(wbase + afro[i]));
            }
            // B fragments: h_hi (and h_lo for hi chunks)
            uint32_t bh[2][2], bl[2][2];
#pragma unroll
            for (int nt = 0; nt < 2; ++nt) {
                int nr = nt * 8 + (lane >> 2);
                int rb = nr * (HSS / 2);
                bh[nt][0] = hs32[rb + hk + (lane & 3)];
                bh[nt][1] = hs32[rb + hk + 4 + (lane & 3)];
                if (hi) {
                    bl[nt][0] = hs32[rb + 160 + hk + (lane & 3)];
                    bl[nt][1] = hs32[rb + 160 + hk + 4 + (lane & 3)];
                }
            }
#define MMA_ACC(ac, Af, B0, B1)                                                     \
    asm volatile("mma.sync.aligned.m16n8k16.row.col.f32.bf16.bf16.f32 "             \
        "{%0,%1,%2,%3}, {%4,%5,%6,%7}, {%8,%9}, {%0,%1,%2,%3};"                     \
        : "+f"((ac)[0]), "+f"((ac)[1]), "+f"((ac)[2]), "+f"((ac)[3])                \
        : "r"((Af)[0]), "r"((Af)[1]), "r"((Af)[2]), "r"((Af)[3]), "r"(B0), "r"(B1))
#pragma unroll
            for (int i = 0; i < 5; ++i)
#pragma unroll
                for (int nt = 0; nt < 2; ++nt)
                    MMA_ACC(acc[i][nt], A[i], bh[nt][0], bh[nt][1]);
            if (hi) {
#pragma unroll
                for (int i = 0; i < 5; ++i)
#pragma unroll
                    for (int nt = 0; nt < 2; ++nt)
                        MMA_ACC(acc[i][nt], A[i], bl[nt][0], bl[nt][1]);
            }
#undef MMA_ACC
            // prefetch chunk kc+4 (wraps to next step) into just-freed stage
            int pfc = kc + 4; if (pfc >= RKC) pfc -= RKC;
            ISSUE_WCHUNK(pfc, stage);
        }

        // write hg preactivations D[row][graph]
#pragma unroll
        for (int i = 0; i < 5; ++i) {
            int r0 = wrow0 + i * 16 + (lane >> 2);
#pragma unroll
            for (int nt = 0; nt < 2; ++nt) {
                int c = nt * 8 + (lane & 3) * 2;
                *(float2*)(Dsm + r0 * 16 + c) = make_float2(acc[i][nt][0], acc[i][nt][1]);
                *(float2*)(Dsm + (r0 + 8) * 16 + c) = make_float2(acc[i][nt][2], acc[i][nt][3]);
            }
        }
        __syncthreads();

        // pointwise GRU update
        for (int it = tid; it < RBT * H; it += RNT) {
            int j = it >> 4, b = it & 15;
            bool valid = t < sln[b];
            size_t ni = (size_t)(sst[b] + t);
            float x0, x1, x2;
            if (valid) {
                const float* xr = xg + ni * G;
                x0 = ldcs(xr + j); x1 = ldcs(xr + H + j); x2 = ldcs(xr + 2 * H + j);
            } else {
                x0 = sbih[j]; x1 = sbih[H + j]; x2 = sbih[2 * H + j];
            }
            float hgr = Dsm[j * 16 + b];
            float hgz = Dsm[(GP + j) * 16 + b];
            float hgn = Dsm[(2 * GP + j) * 16 + b];
            float r  = sigm(x0 + hgr + sbhh[j]);
            float z  = sigm(x1 + hgz + sbhh[H + j]);
            float nn = tanh_fast(x2 + r * (hgn + sbhh[2 * H + j]));
            float hp = hf[b * HFS + j];
            float hv = (1.f - z) * nn + z * hp;
            hf[b * HFS + j] = hv;
            __nv_bfloat16 hi = __float2bfloat16(hv);
            hsb[b * HSS + j] = hi;
            hsb[b * HSS + 320 + j] = __float2bfloat16(hv - __bfloat162float(hi));
            if (valid) stcs(out + ni * (2 * H) + dir * H + j, hv);
        }
        __syncthreads();
    }
    asm volatile("cp.async.wait_group 0;" ::: "memory");   // drain before exit
#undef ISSUE_WCHUNK
}

// ---------------- host entry ----------------
extern "C" void kernel_launch(void* const* d_in, const int* in_sizes, int n_in,
                              void* d_out, int out_size) {
    const float* node   = (const float*)d_in[0];
    const int*   batch  = (const int*)d_in[1];
    const int*   pos    = (const int*)d_in[2];
    const float* bias   = (const float*)d_in[3];
    const float* w_ih_f = (const float*)d_in[4];
    const float* w_hh_f = (const float*)d_in[5];
    const float* b_ih_f = (const float*)d_in[6];
    const float* b_hh_f = (const float*)d_in[7];
    const float* w_ih_b = (const float*)d_in[8];
    const float* w_hh_b = (const float*)d_in[9];
    const float* b_ih_b = (const float*)d_in[10];
    const float* b_hh_b = (const float*)d_in[11];
    float* out = (float*)d_out;
    int n = in_sizes[0] / H;

    cudaFuncSetAttribute(k_recur_mma, cudaFuncAttributeMaxDynamicSharedMemorySize, SM_TOT);

    k_seg<<<(n + 255) / 256, 256>>>(batch, pos, n);
    k_h0<<<NB, NTHREADS>>>(node);
    k_convA<<<n, 256>>>(node, bias, n);
    k_convB<<<2048, 256>>>(w_ih_f, w_ih_b);
    k_convW<<<1024, 256>>>(w_hh_f, w_hh_b);
    k_gemm_mma<<<dim3(16, n / MT), 256>>>(b_ih_f, b_ih_b);
    k_recur_mma<<<dim3(NB / RBT, 2), RNT, SM_TOT>>>(b_ih_f, b_ih_b, b_hh_f, b_hh_b, out);
}

// round 8
// speedup vs baseline: 2.1502x; 1.0462x over previous
#include <cuda_runtime.h>
#include <cuda_bf16.h>
#include <math.h>
#include <cstdint>

#define H     300
#define G     900
#define NB    1024
#define LSEQ  64
#define NTHREADS 320
#define NNODES 49152

// ---- input GEMM config ----
#define KP  960
#define NP  1024
#define MT  128
#define NKB2 (KP / 32)
#define SROW 80
#define GSTG 20480            // one stage: A(128x80) + B(128x80)
#define GSM_TOT (3 * GSTG)    // 61440 B dynamic smem, 3 stages

// ---- recurrent mma config ----
#define GP    320
#define RROWS 960
#define RKC   38
#define WSTG  (RROWS * 32)
#define HSS   648
#define HFS   304
#define RBT   16
#define RNT   384

#define SM_W    0
#define SM_D    (4 * WSTG)
#define SM_HS   (SM_D + RROWS * 16 * 4)
#define SM_HF   (SM_HS + RBT * HSS * 2)
#define SM_BH   (SM_HF + RBT * HFS * 4)
#define SM_BI   (SM_BH + 3600)
#define SM_MISC (SM_BI + 3600)
#define SM_TOT  (SM_MISC + 128)

__device__ __forceinline__ float sigm(float x) { return 1.f / (1.f + __expf(-x)); }
__device__ __forceinline__ float tanh_fast(float x) {
    float s = 1.f / (1.f + __expf(-2.f * x));
    return 2.f * s - 1.f;
}
__device__ __forceinline__ uint32_t smem_u32(const void* p) {
    uint32_t a;
    asm("{ .reg .u64 t; cvta.to.shared.u64 t, %1; cvt.u32.u64 %0, t; }" : "=r"(a) : "l"(p));
    return a;
}
__device__ __forceinline__ float ldcs(const float* p) {
    float v; asm volatile("ld.global.cs.f32 %0, [%1];" : "=f"(v) : "l"(p)); return v;
}
__device__ __forceinline__ void stcs(float* p, float v) {
    asm volatile("st.global.cs.f32 [%0], %1;" :: "l"(p), "f"(v));
}

// ---------------- device scratch ----------------
__device__ __align__(16) __nv_bfloat16 g_abf[(size_t)NNODES * KP];
__device__ __align__(16) __nv_bfloat16 g_bbf[2][(size_t)NP * KP];
__device__ __align__(16) __nv_bfloat16 g_gwr[(size_t)2 * RKC * RROWS * 16];
__device__ float g_xg[2][(size_t)NNODES * G];
__device__ float g_h0[NB * H];
__device__ int   g_sstart[NB];
__device__ int   g_slen[NB];

// ---------------- 1) merged prep: seg | convA | convB | convW ----------------
__global__ void __launch_bounds__(256) k_prep(const float* __restrict__ node,
                                              const float* __restrict__ bias,
                                              const int* __restrict__ batch,
                                              const int* __restrict__ pos,
                                              const float* __restrict__ wif,
                                              const float* __restrict__ wib,
                                              const float* __restrict__ whf,
                                              const float* __restrict__ whb,
                                              int n) {
    __shared__ float sb[H];
    const int bx = blockIdx.x, tid = threadIdx.x;
    if (bx < 64) {
        // ---- segment bounds ----
        for (int i = bx * 256 + tid; i < n; i += 64 * 256) {
            int b = batch[i];
            if (pos[i] == 0) g_sstart[b] = i;
            if (i == n - 1 || batch[i + 1] != b) g_slen[b] = pos[i] + 1;
        }
    } else if (bx < 64 + n) {
        // ---- convA: one block per node ----
        int i = bx - 64;
        for (int k = tid; k < H; k += 256) {
            float v = node[(size_t)i * H + k] + bias[k];
            sb[k] = v > 0.f ? v : 0.f;
        }
        __syncthreads();
        __nv_bfloat16* dst = g_abf + (size_t)i * KP;
        for (int kp = tid; kp < KP; kp += 256) {
            __nv_bfloat16 o = __float2bfloat16(0.f);
            int k = -1; bool lo = false;
            if (kp < 300)                    { k = kp; }
            else if (kp >= 320 && kp < 620)  { k = kp - 320; lo = true; }
            else if (kp >= 640 && kp < 940)  { k = kp - 640; }
            if (k >= 0) {
                float m = sb[k];
                __nv_bfloat16 hi = __float2bfloat16(m);
                o = lo ? __float2bfloat16(m - __bfloat162float(hi)) : hi;
            }
            dst[kp] = o;
        }
    } else if (bx < 64 + n + 512) {
        // ---- convB ----
        size_t tot = (size_t)2 * NP * KP;
        int bb = bx - 64 - n;
        for (size_t idx = (size_t)bb * 256 + tid; idx < tot; idx += (size_t)512 * 256) {
            int dir = (int)(idx / ((size_t)NP * KP));
            size_t r = idx - (size_t)dir * NP * KP;
            int g = (int)(r / KP), kp = (int)(r - (size_t)g * KP);
            __nv_bfloat16 o = __float2bfloat16(0.f);
            int k = -1; bool lo = false;
            if (kp < 300)                    { k = kp; }
            else if (kp >= 320 && kp < 620)  { k = kp - 320; }
            else if (kp >= 640 && kp < 940)  { k = kp - 640; lo = true; }
            if (k >= 0 && g < G) {
                const float* w = dir ? wib : wif;
                float v = w[(size_t)g * H + k];
                __nv_bfloat16 hi = __float2bfloat16(v);
                o = lo ? __float2bfloat16(v - __bfloat162float(hi)) : hi;
            }
            g_bbf[dir][r] = o;
        }
    } else {
        // ---- convW ----
        const int tot = 2 * RKC * RROWS * 16;
        int bb = bx - 64 - n - 512;
        for (int idx = bb * 256 + tid; idx < tot; idx += 256 * 256) {
            int dir = idx / (RKC * RROWS * 16);
            int r = idx % (RKC * RROWS * 16);
            int kc = r / (RROWS * 16);
            int rr = r % (RROWS * 16);
            int row = rr >> 4, c = rr & 15;
            int gate = row / GP, j = row % GP;
            bool lo = kc >= 19;
            int k = (lo ? kc - 19 : kc) * 16 + c;
            __nv_bfloat16 o = __float2bfloat16(0.f);
            if (j < H && k < H) {
                const float* w = dir ? whb : whf;
                float v = w[(size_t)(gate * H + j) * H + k];
                __nv_bfloat16 hi = __float2bfloat16(v);
                o = lo ? __float2bfloat16(v - __bfloat162float(hi)) : hi;
            }
            g_gwr[idx] = o;
        }
    }
}

// ---------------- 2) h0 = per-graph segment max ----------------
__global__ void __launch_bounds__(NTHREADS) k_h0(const float* __restrict__ node) {
    int b = blockIdx.x, h = threadIdx.x;
    if (h >= H) return;
    int s = g_sstart[b], l = g_slen[b];
    float m = -3.402823466e38f;
    for (int i = 0; i < l; ++i) m = fmaxf(m, node[(size_t)(s + i) * H + h]);
    g_h0[b * H + h] = m;
}

// ---------------- 3) input GEMM: 3-stage pipeline, tail-tile trim ----------------
__global__ void __launch_bounds__(256, 2) k_gemm_mma(const float* __restrict__ bih_f,
                                                     const float* __restrict__ bih_b) {
    extern __shared__ unsigned char gsm[];
    const int tid = threadIdx.x, lane = tid & 31, wid = tid >> 5;
    const int dir = blockIdx.x >> 3, ntile = blockIdx.x & 7;
    const int m0 = blockIdx.y * MT, n0 = ntile * 128;
    const int wm = wid & 3, wn = wid >> 2;

    const __nv_bfloat16* __restrict__ A = g_abf + (size_t)m0 * KP;
    const __nv_bfloat16* __restrict__ B = g_bbf[dir] + (size_t)n0 * KP;
    const uint32_t s0 = smem_u32(gsm);

    float d[2][8][4];
#pragma unroll
    for (int mi = 0; mi < 2; ++mi)
#pragma unroll
        for (int ni = 0; ni < 8; ++ni)
#pragma unroll
            for (int e = 0; e < 4; ++e) d[mi][ni][e] = 0.f;

#define ISSUE_STAGE(kb, stg) do {                                                   \
    _Pragma("unroll")                                                               \
    for (int _p = 0; _p < 2; ++_p) {                                                \
        int _u = _p * 256 + tid, _row = _u >> 2, _c = _u & 3;                       \
        const void* _ga = A + (size_t)_row * KP + (kb) * 32 + _c * 8;               \
        uint32_t _da = s0 + (stg) * GSTG + _row * SROW + _c * 16;                   \
        asm volatile("cp.async.cg.shared.global [%0], [%1], 16;" :: "r"(_da), "l"(_ga)); \
        const void* _gb = B + (size_t)_row * KP + (kb) * 32 + _c * 8;               \
        uint32_t _db = s0 + (stg) * GSTG + 10240 + _row * SROW + _c * 16;           \
        asm volatile("cp.async.cg.shared.global [%0], [%1], 16;" :: "r"(_db), "l"(_gb)); \
    }                                                                               \
    asm volatile("cp.async.commit_group;" ::: "memory");                            \
} while (0)

#define GEMM_COMPUTE(a32, b32, NIMAX)                                               \
    _Pragma("unroll")                                                               \
    for (int ks = 0; ks < 2; ++ks) {                                                \
        uint32_t af[2][4];                                                          \
        _Pragma("unroll")                                                           \
        for (int mi = 0; mi < 2; ++mi) {                                            \
            int r0 = wm * 32 + mi * 16 + (lane >> 2);                               \
            af[mi][0] = (a32)[r0 * 20 + ks * 8 + (lane & 3)];                       \
            af[mi][1] = (a32)[(r0 + 8) * 20 + ks * 8 + (lane & 3)];                 \
            af[mi][2] = (a32)[r0 * 20 + ks * 8 + 4 + (lane & 3)];                   \
            af[mi][3] = (a32)[(r0 + 8) * 20 + ks * 8 + 4 + (lane & 3)];             \
        }                                                                           \
        _Pragma("unroll")                                                           \
        for (int ni = 0; ni < (NIMAX); ++ni) {                                      \
            int cn = wn * 64 + ni * 8 + (lane >> 2);                                \
            uint32_t b0 = (b32)[cn * 20 + ks * 8 + (lane & 3)];                     \
            uint32_t b1 = (b32)[cn * 20 + ks * 8 + 4 + (lane & 3)];                 \
            _Pragma("unroll")                                                       \
            for (int mi = 0; mi < 2; ++mi) {                                        \
                asm volatile(                                                       \
                    "mma.sync.aligned.m16n8k16.row.col.f32.bf16.bf16.f32 "          \
                    "{%0,%1,%2,%3}, {%4,%5,%6,%7}, {%8,%9}, {%0,%1,%2,%3};"         \
                    : "+f"(d[mi][ni][0]), "+f"(d[mi][ni][1]),                       \
                      "+f"(d[mi][ni][2]), "+f"(d[mi][ni][3])                        \
                    : "r"(af[mi][0]), "r"(af[mi][1]), "r"(af[mi][2]), "r"(af[mi][3]), \
                      "r"(b0), "r"(b1));                                            \
            }                                                                       \
        }                                                                           \
    }

    ISSUE_STAGE(0, 0);
    ISSUE_STAGE(1, 1);
    const bool tail = (ntile == 7);
    int stg = 0;
    for (int kb = 0; kb < NKB2; ++kb) {
        if (kb <= NKB2 - 2) { asm volatile("cp.async.wait_group 1;" ::: "memory"); }
        else                { asm volatile("cp.async.wait_group 0;" ::: "memory"); }
        __syncthreads();
        const uint32_t* a32 = (const uint32_t*)(gsm + stg * GSTG);
        const uint32_t* b32 = (const uint32_t*)(gsm + stg * GSTG + 10240);
        if (!tail) { GEMM_COMPUTE(a32, b32, 8); }
        else       { GEMM_COMPUTE(a32, b32, 1); }
        if (kb + 2 < NKB2) {
            int ns = stg + 2; if (ns >= 3) ns -= 3;
            ISSUE_STAGE(kb + 2, ns);
        }
        if (++stg == 3) stg = 0;
    }
#undef ISSUE_STAGE
#undef GEMM_COMPUTE

    const float* __restrict__ bih = dir ? bih_b : bih_f;
    float* __restrict__ xg = g_xg[dir];
    const int nimax = tail ? 1 : 8;
#pragma unroll
    for (int mi = 0; mi < 2; ++mi) {
        int r0 = m0 + wm * 32 + mi * 16 + (lane >> 2);
        for (int ni = 0; ni < nimax; ++ni) {
            int g = n0 + wn * 64 + ni * 8 + (lane & 3) * 2;
            if (g < G) {
                float bg0 = bih[g], bg1 = bih[g + 1];
                *(float2*)(xg + (size_t)r0 * G + g) =
                    make_float2(d[mi][ni][0] + bg0, d[mi][ni][1] + bg1);
                *(float2*)(xg + (size_t)(r0 + 8) * G + g) =
                    make_float2(d[mi][ni][2] + bg0, d[mi][ni][3] + bg1);
            }
        }
    }
}

// ---------------- 4) recurrent GRU via mma.sync (proven round-7) ----------------
__global__ void __launch_bounds__(RNT, 1) k_recur_mma(const float* __restrict__ bih_f,
                                                      const float* __restrict__ bih_b,
                                                      const float* __restrict__ bhh_f,
                                                      const float* __restrict__ bhh_b,
                                                      float* __restrict__ out) {
    extern __shared__ char smem[];
    float*           Dsm  = (float*)(smem + SM_D);
    uint32_t*        hs32 = (uint32_t*)(smem + SM_HS);
    __nv_bfloat16*   hsb  = (__nv_bfloat16*)(smem + SM_HS);
    float*           hf   = (float*)(smem + SM_HF);
    float*           sbhh = (float*)(smem + SM_BH);
    float*           sbih = (float*)(smem + SM_BI);
    int*             sst  = (int*)(smem + SM_MISC);
    int*             sln  = sst + RBT;

    const int tid = threadIdx.x, lane = tid & 31, wid = tid >> 5;
    const int dir = blockIdx.y;
    const int b0 = blockIdx.x * RBT;
    const int wrow0 = wid * 80;
    const uint32_t swb = smem_u32(smem);

    uint32_t afro[5];
    {
        int lsel = lane >> 3, lrow = lane & 7;
        int half = lsel >> 1;
#pragma unroll
        for (int i = 0; i < 5; ++i) {
            int row = wrow0 + i * 16 + lrow + ((lsel & 1) << 3);
            afro[i] = row * 32 + ((half ^ ((row >> 2) & 1)) << 4);
        }
    }

    const __nv_bfloat16* __restrict__ gw = g_gwr + (size_t)dir * RKC * RROWS * 16;
    const float* __restrict__ xg = g_xg[dir];

#define ISSUE_WCHUNK(pfc, stg) do {                                                 \
    const char* _src = (const char*)(gw + (size_t)(pfc) * (RROWS * 16)) + wrow0 * 32; \
    _Pragma("unroll")                                                               \
    for (int _i = 0; _i < 5; ++_i) {                                                \
        int _fl = lane + 32 * _i;                                                   \
        int _row = _fl >> 1, _half = _fl & 1;                                       \
        int _ar = wrow0 + _row;                                                     \
        int _hsw = _half ^ ((_ar >> 2) & 1);                                        \
        uint32_t _d = swb + (stg) * WSTG + _ar * 32 + (_hsw << 4);                  \
        const void* _s = _src + _row * 32 + _half * 16;                             \
        asm volatile("cp.async.cg.shared.global [%0], [%1], 16;" :: "r"(_d), "l"(_s)); \
    }                                                                               \
    asm volatile("cp.async.commit_group;" ::: "memory");                            \
} while (0)

#pragma unroll
    for (int p = 0; p < 4; ++p) ISSUE_WCHUNK(p, p);

    if (tid < RBT) { sst[tid] = g_sstart[b0 + tid]; sln[tid] = g_slen[b0 + tid]; }
    for (int i = tid; i < RBT * (HSS / 2); i += RNT) hs32[i] = 0u;
    {
        const float* bhh = dir ? bhh_b : bhh_f;
        const float* bih = dir ? bih_b : bih_f;
        for (int i = tid; i < G; i += RNT) { sbhh[i] = bhh[i]; sbih[i] = bih[i]; }
    }
    __syncthreads();
    for (int it = tid; it < RBT * H; it += RNT) {
        int j = it >> 4, b = it & 15;
        float v = g_h0[(b0 + b) * H + j];
        hf[b * HFS + j] = v;
        __nv_bfloat16 hi = __float2bfloat16(v);
        hsb[b * HSS + j] = hi;
        hsb[b * HSS + 320 + j] = __float2bfloat16(v - __bfloat162float(hi));
    }
    __syncthreads();

    for (int s = 0; s < LSEQ; ++s) {
        int t = dir ? (LSEQ - 1 - s) : s;
        float acc[5][2][4];
#pragma unroll
        for (int i = 0; i < 5; ++i)
#pragma unroll
            for (int nt = 0; nt < 2; ++nt)
#pragma unroll
                for (int e = 0; e < 4; ++e) acc[i][nt][e] = 0.f;

        const int sbase = 2 * (s & 1);
#pragma unroll 1
        for (int kc = 0; kc < RKC; ++kc) {
            const int stage = (kc + sbase) & 3;
            asm volatile("cp.async.wait_group 3;" ::: "memory");
            const uint32_t wbase = swb + (uint32_t)stage * WSTG;
            const bool hi = (kc < 19);
            const int hk = (hi ? kc : kc - 19) * 8;

            uint32_t A[5][4];
#pragma unroll
            for (int i = 0; i < 5; ++i) {
                asm volatile("ldmatrix.sync.aligned.m8n8.x4.shared.b16 "
                             "{%0,%1,%2,%3}, [%4];"
                             : "=r"(A[i][0]), "=r"(A[i][1]), "=r"(A[i][2]), "=r"(A[i][3])
                             : "r"(wbase + afro[i]));
            }
            uint32_t bh[2][2], bl[2][2];
#pragma unroll
            for (int nt = 0; nt < 2; ++nt) {
                int nr = nt * 8 + (lane >> 2);
                int rb = nr * (HSS / 2);
                bh[nt][0] = hs32[rb + hk + (lane & 3)];
                bh[nt][1] = hs32[rb + hk + 4 + (lane & 3)];
                if (hi) {
                    bl[nt][0] = hs32[rb + 160 + hk + (lane & 3)];
                    bl[nt][1] = hs32[rb + 160 + hk + 4 + (lane & 3)];
                }
            }
#define MMA_ACC(ac, Af, B0, B1)                                                     \
    asm volatile("mma.sync.aligned.m16n8k16.row.col.f32.bf16.bf16.f32 "             \
        "{%0,%1,%2,%3}, {%4,%5,%6,%7}, {%8,%9}, {%0,%1,%2,%3};"                     \
        : "+f"((ac)[0]), "+f"((ac)[1]), "+f"((ac)[2]), "+f"((ac)[3])                \
        : "r"((Af)[0]), "r"((Af)[1]), "r"((Af)[2]), "r"((Af)[3]), "r"(B0), "r"(B1))
#pragma unroll
            for (int i = 0; i < 5; ++i)
#pragma unroll
                for (int nt = 0; nt < 2; ++nt)
                    MMA_ACC(acc[i][nt], A[i], bh[nt][0], bh[nt][1]);
            if (hi) {
#pragma unroll
                for (int i = 0; i < 5; ++i)
#pragma unroll
                    for (int nt = 0; nt < 2; ++nt)
                        MMA_ACC(acc[i][nt], A[i], bl[nt][0], bl[nt][1]);
            }
#undef MMA_ACC
            int pfc = kc + 4; if (pfc >= RKC) pfc -= RKC;
            ISSUE_WCHUNK(pfc, stage);
        }

#pragma unroll
        for (int i = 0; i < 5; ++i) {
            int r0 = wrow0 + i * 16 + (lane >> 2);
#pragma unroll
            for (int nt = 0; nt < 2; ++nt) {
                int c = nt * 8 + (lane & 3) * 2;
                *(float2*)(Dsm + r0 * 16 + c) = make_float2(acc[i][nt][0], acc[i][nt][1]);
                *(float2*)(Dsm + (r0 + 8) * 16 + c) = make_float2(acc[i][nt][2], acc[i][nt][3]);
            }
        }
        __syncthreads();

        for (int it = tid; it < RBT * H; it += RNT) {
            int j = it >> 4, b = it & 15;
            bool valid = t < sln[b];
            size_t ni = (size_t)(sst[b] + t);
            float x0, x1, x2;
            if (valid) {
                const float* xr = xg + ni * G;
                x0 = ldcs(xr + j); x1 = ldcs(xr + H + j); x2 = ldcs(xr + 2 * H + j);
            } else {
                x0 = sbih[j]; x1 = sbih[H + j]; x2 = sbih[2 * H + j];
            }
            float hgr = Dsm[j * 16 + b];
            float hgz = Dsm[(GP + j) * 16 + b];
            float hgn = Dsm[(2 * GP + j) * 16 + b];
            float r  = sigm(x0 + hgr + sbhh[j]);
            float z  = sigm(x1 + hgz + sbhh[H + j]);
            float nn = tanh_fast(x2 + r * (hgn + sbhh[2 * H + j]));
            float hp = hf[b * HFS + j];
            float hv = (1.f - z) * nn + z * hp;
            hf[b * HFS + j] = hv;
            __nv_bfloat16 hi = __float2bfloat16(hv);
            hsb[b * HSS + j] = hi;
            hsb[b * HSS + 320 + j] = __float2bfloat16(hv - __bfloat162float(hi));
            if (valid) stcs(out + ni * (2 * H) + dir * H + j, hv);
        }
        __syncthreads();
    }
    asm volatile("cp.async.wait_group 0;" ::: "memory");
#undef ISSUE_WCHUNK
}

// ---------------- host entry ----------------
extern "C" void kernel_launch(void* const* d_in, const int* in_sizes, int n_in,
                              void* d_out, int out_size) {
    const float* node   = (const float*)d_in[0];
    const int*   batch  = (const int*)d_in[1];
    const int*   pos    = (const int*)d_in[2];
    const float* bias   = (const float*)d_in[3];
    const float* w_ih_f = (const float*)d_in[4];
    const float* w_hh_f = (const float*)d_in[5];
    const float* b_ih_f = (const float*)d_in[6];
    const float* b_hh_f = (const float*)d_in[7];
    const float* w_ih_b = (const float*)d_in[8];
    const float* w_hh_b = (const float*)d_in[9];
    const float* b_ih_b = (const float*)d_in[10];
    const float* b_hh_b = (const float*)d_in[11];
    float* out = (float*)d_out;
    int n = in_sizes[0] / H;

    cudaFuncSetAttribute(k_gemm_mma, cudaFuncAttributeMaxDynamicSharedMemorySize, GSM_TOT);
    cudaFuncSetAttribute(k_recur_mma, cudaFuncAttributeMaxDynamicSharedMemorySize, SM_TOT);

    int gprep = 64 + n + 512 + 256;
    k_prep<<<gprep, 256>>>(node, bias, batch, pos, w_ih_f, w_ih_b, w_hh_f, w_hh_b, n);
    k_h0<<<NB, NTHREADS>>>(node);
    k_gemm_mma<<<dim3(16, n / MT), 256, GSM_TOT>>>(b_ih_f, b_ih_b);
    k_recur_mma<<<dim3(NB / RBT, 2), RNT, SM_TOT>>>(b_ih_f, b_ih_b, b_hh_f, b_hh_b, out);
}

// round 9
// speedup vs baseline: 2.1610x; 1.0050x over previous
#include <cuda_runtime.h>
#include <cuda_bf16.h>
#include <math.h>
#include <cstdint>

#define H     300
#define G     900
#define NB    1024
#define LSEQ  64
#define NTHREADS 320
#define NNODES 49152

// ---- input GEMM config ----
#define KP  960
#define NP  1024
#define MT  128
#define NKB2 (KP / 32)
#define SROW 80
#define GSTG 20480            // one stage: A(128x80) + B(128x80)
#define GSM_TOT (3 * GSTG)    // 61440 B dynamic smem, 3 stages

// ---- recurrent mma config ----
#define GP    320
#define RROWS 960
#define RKC   38
#define WSTG  (RROWS * 32)
#define HSS   648
#define HFS   304
#define RBT   16
#define RNT   384

#define SM_W    0
#define SM_D    (4 * WSTG)
#define SM_HS   (SM_D + RROWS * 16 * 4)
#define SM_HF   (SM_HS + RBT * HSS * 2)
#define SM_BH   (SM_HF + RBT * HFS * 4)
#define SM_BI   (SM_BH + 3600)
#define SM_MISC (SM_BI + 3600)
#define SM_TOT  (SM_MISC + 128)

__device__ __forceinline__ float sigm(float x) { return 1.f / (1.f + __expf(-x)); }
__device__ __forceinline__ float tanh_fast(float x) {
    float s = 1.f / (1.f + __expf(-2.f * x));
    return 2.f * s - 1.f;
}
__device__ __forceinline__ uint32_t smem_u32(const void* p) {
    uint32_t a;
    asm("{ .reg .u64 t; cvta.to.shared.u64 t, %1; cvt.u32.u64 %0, t; }" : "=r"(a) : "l"(p));
    return a;
}
__device__ __forceinline__ float ldcs(const float* p) {
    float v; asm volatile("ld.global.cs.f32 %0, [%1];" : "=f"(v) : "l"(p)); return v;
}
__device__ __forceinline__ void stcs(float* p, float v) {
    asm volatile("st.global.cs.f32 [%0], %1;" :: "l"(p), "f"(v));
}

// ---------------- device scratch ----------------
__device__ __align__(16) __nv_bfloat16 g_abf[(size_t)NNODES * KP];
__device__ __align__(16) __nv_bfloat16 g_bbf[2][(size_t)NP * KP];
__device__ __align__(16) __nv_bfloat16 g_gwr[(size_t)2 * RKC * RROWS * 16];
__device__ float g_xg[2][(size_t)NNODES * G];
__device__ float g_h0[NB * H];
__device__ int   g_sstart[NB];
__device__ int   g_slen[NB];

// ---------------- 1) merged prep: seg | convA | convB | convW ----------------
__global__ void __launch_bounds__(256) k_prep(const float* __restrict__ node,
                                              const float* __restrict__ bias,
                                              const int* __restrict__ batch,
                                              const int* __restrict__ pos,
                                              const float* __restrict__ wif,
                                              const float* __restrict__ wib,
                                              const float* __restrict__ whf,
                                              const float* __restrict__ whb,
                                              int n) {
    __shared__ float sb[H];
    const int bx = blockIdx.x, tid = threadIdx.x;
    if (bx < 64) {
        for (int i = bx * 256 + tid; i < n; i += 64 * 256) {
            int b = batch[i];
            if (pos[i] == 0) g_sstart[b] = i;
            if (i == n - 1 || batch[i + 1] != b) g_slen[b] = pos[i] + 1;
        }
    } else if (bx < 64 + n) {
        int i = bx - 64;
        for (int k = tid; k < H; k += 256) {
            float v = node[(size_t)i * H + k] + bias[k];
            sb[k] = v > 0.f ? v : 0.f;
        }
        __syncthreads();
        __nv_bfloat16* dst = g_abf + (size_t)i * KP;
        for (int kp = tid; kp < KP; kp += 256) {
            __nv_bfloat16 o = __float2bfloat16(0.f);
            int k = -1; bool lo = false;
            if (kp < 300)                    { k = kp; }
            else if (kp >= 320 && kp < 620)  { k = kp - 320; lo = true; }
            else if (kp >= 640 && kp < 940)  { k = kp - 640; }
            if (k >= 0) {
                float m = sb[k];
                __nv_bfloat16 hi = __float2bfloat16(m);
                o = lo ? __float2bfloat16(m - __bfloat162float(hi)) : hi;
            }
            dst[kp] = o;
        }
    } else if (bx < 64 + n + 512) {
        size_t tot = (size_t)2 * NP * KP;
        int bb = bx - 64 - n;
        for (size_t idx = (size_t)bb * 256 + tid; idx < tot; idx += (size_t)512 * 256) {
            int dir = (int)(idx / ((size_t)NP * KP));
            size_t r = idx - (size_t)dir * NP * KP;
            int g = (int)(r / KP), kp = (int)(r - (size_t)g * KP);
            __nv_bfloat16 o = __float2bfloat16(0.f);
            int k = -1; bool lo = false;
            if (kp < 300)                    { k = kp; }
            else if (kp >= 320 && kp < 620)  { k = kp - 320; }
            else if (kp >= 640 && kp < 940)  { k = kp - 640; lo = true; }
            if (k >= 0 && g < G) {
                const float* w = dir ? wib : wif;
                float v = w[(size_t)g * H + k];
                __nv_bfloat16 hi = __float2bfloat16(v);
                o = lo ? __float2bfloat16(v - __bfloat162float(hi)) : hi;
            }
            g_bbf[dir][r] = o;
        }
    } else {
        const int tot = 2 * RKC * RROWS * 16;
        int bb = bx - 64 - n - 512;
        for (int idx = bb * 256 + tid; idx < tot; idx += 256 * 256) {
            int dir = idx / (RKC * RROWS * 16);
            int r = idx % (RKC * RROWS * 16);
            int kc = r / (RROWS * 16);
            int rr = r % (RROWS * 16);
            int row = rr >> 4, c = rr & 15;
            int gate = row / GP, j = row % GP;
            bool lo = kc >= 19;
            int k = (lo ? kc - 19 : kc) * 16 + c;
            __nv_bfloat16 o = __float2bfloat16(0.f);
            if (j < H && k < H) {
                const float* w = dir ? whb : whf;
                float v = w[(size_t)(gate * H + j) * H + k];
                __nv_bfloat16 hi = __float2bfloat16(v);
                o = lo ? __float2bfloat16(v - __bfloat162float(hi)) : hi;
            }
            g_gwr[idx] = o;
        }
    }
}

// ---------------- 2) h0 = per-graph segment max ----------------
__global__ void __launch_bounds__(NTHREADS) k_h0(const float* __restrict__ node) {
    int b = blockIdx.x, h = threadIdx.x;
    if (h >= H) return;
    int s = g_sstart[b], l = g_slen[b];
    float m = -3.402823466e38f;
    for (int i = 0; i < l; ++i) m = fmaxf(m, node[(size_t)(s + i) * H + h]);
    g_h0[b * H + h] = m;
}

// ---------------- 3) input GEMM: 3-stage pipeline, tail-tile trim ----------------
__global__ void __launch_bounds__(256, 2) k_gemm_mma(const float* __restrict__ bih_f,
                                                     const float* __restrict__ bih_b) {
    extern __shared__ unsigned char gsm[];
    const int tid = threadIdx.x, lane = tid & 31, wid = tid >> 5;
    const int dir = blockIdx.x >> 3, ntile = blockIdx.x & 7;
    const int m0 = blockIdx.y * MT, n0 = ntile * 128;
    const int wm = wid & 3, wn = wid >> 2;

    const __nv_bfloat16* __restrict__ A = g_abf + (size_t)m0 * KP;
    const __nv_bfloat16* __restrict__ B = g_bbf[dir] + (size_t)n0 * KP;
    const uint32_t s0 = smem_u32(gsm);

    float d[2][8][4];
#pragma unroll
    for (int mi = 0; mi < 2; ++mi)
#pragma unroll
        for (int ni = 0; ni < 8; ++ni)
#pragma unroll
            for (int e = 0; e < 4; ++e) d[mi][ni][e] = 0.f;

#define ISSUE_STAGE(kb, stg) do {                                                   \
    _Pragma("unroll")                                                               \
    for (int _p = 0; _p < 2; ++_p) {                                                \
        int _u = _p * 256 + tid, _row = _u >> 2, _c = _u & 3;                       \
        const void* _ga = A + (size_t)_row * KP + (kb) * 32 + _c * 8;               \
        uint32_t _da = s0 + (stg) * GSTG + _row * SROW + _c * 16;                   \
        asm volatile("cp.async.cg.shared.global [%0], [%1], 16;" :: "r"(_da), "l"(_ga)); \
        const void* _gb = B + (size_t)_row * KP + (kb) * 32 + _c * 8;               \
        uint32_t _db = s0 + (stg) * GSTG + 10240 + _row * SROW + _c * 16;           \
        asm volatile("cp.async.cg.shared.global [%0], [%1], 16;" :: "r"(_db), "l"(_gb)); \
    }                                                                               \
    asm volatile("cp.async.commit_group;" ::: "memory");                            \
} while (0)

#define GEMM_COMPUTE(a32, b32, NIMAX)                                               \
    _Pragma("unroll")                                                               \
    for (int ks = 0; ks < 2; ++ks) {                                                \
        uint32_t af[2][4];                                                          \
        _Pragma("unroll")                                                           \
        for (int mi = 0; mi < 2; ++mi) {                                            \
            int r0 = wm * 32 + mi * 16 + (lane >> 2);                               \
            af[mi][0] = (a32)[r0 * 20 + ks * 8 + (lane & 3)];                       \
            af[mi][1] = (a32)[(r0 + 8) * 20 + ks * 8 + (lane & 3)];                 \
            af[mi][2] = (a32)[r0 * 20 + ks * 8 + 4 + (lane & 3)];                   \
            af[mi][3] = (a32)[(r0 + 8) * 20 + ks * 8 + 4 + (lane & 3)];             \
        }                                                                           \
        _Pragma("unroll")                                                           \
        for (int ni = 0; ni < (NIMAX); ++ni) {                                      \
            int cn = wn * 64 + ni * 8 + (lane >> 2);                                \
            uint32_t b0 = (b32)[cn * 20 + ks * 8 + (lane & 3)];                     \
            uint32_t b1 = (b32)[cn * 20 + ks * 8 + 4 + (lane & 3)];                 \
            _Pragma("unroll")                                                       \
            for (int mi = 0; mi < 2; ++mi) {                                        \
                asm volatile(                                                       \
                    "mma.sync.aligned.m16n8k16.row.col.f32.bf16.bf16.f32 "          \
                    "{%0,%1,%2,%3}, {%4,%5,%6,%7}, {%8,%9}, {%0,%1,%2,%3};"         \
                    : "+f"(d[mi][ni][0]), "+f"(d[mi][ni][1]),                       \
                      "+f"(d[mi][ni][2]), "+f"(d[mi][ni][3])                        \
                    : "r"(af[mi][0]), "r"(af[mi][1]), "r"(af[mi][2]), "r"(af[mi][3]), \
                      "r"(b0), "r"(b1));                                            \
            }                                                                       \
        }                                                                           \
    }

    ISSUE_STAGE(0, 0);
    ISSUE_STAGE(1, 1);
    const bool tail = (ntile == 7);
    int stg = 0;
    for (int kb = 0; kb < NKB2; ++kb) {
        if (kb <= NKB2 - 2) { asm volatile("cp.async.wait_group 1;" ::: "memory"); }
        else                { asm volatile("cp.async.wait_group 0;" ::: "memory"); }
        __syncthreads();
        const uint32_t* a32 = (const uint32_t*)(gsm + stg * GSTG);
        const uint32_t* b32 = (const uint32_t*)(gsm + stg * GSTG + 10240);
        if (!tail) { GEMM_COMPUTE(a32, b32, 8); }
        else       { GEMM_COMPUTE(a32, b32, 1); }
        if (kb + 2 < NKB2) {
            int ns = stg + 2; if (ns >= 3) ns -= 3;
            ISSUE_STAGE(kb + 2, ns);
        }
        if (++stg == 3) stg = 0;
    }
#undef ISSUE_STAGE
#undef GEMM_COMPUTE

    const float* __restrict__ bih = dir ? bih_b : bih_f;
    float* __restrict__ xg = g_xg[dir];
    const int nimax = tail ? 1 : 8;
#pragma unroll
    for (int mi = 0; mi < 2; ++mi) {
        int r0 = m0 + wm * 32 + mi * 16 + (lane >> 2);
        for (int ni = 0; ni < nimax; ++ni) {
            int g = n0 + wn * 64 + ni * 8 + (lane & 3) * 2;
            if (g < G) {
                float bg0 = bih[g], bg1 = bih[g + 1];
                *(float2*)(xg + (size_t)r0 * G + g) =
                    make_float2(d[mi][ni][0] + bg0, d[mi][ni][1] + bg1);
                *(float2*)(xg + (size_t)(r0 + 8) * G + g) =
                    make_float2(d[mi][ni][2] + bg0, d[mi][ni][3] + bg1);
            }
        }
    }
}

// ---------------- 4) recurrent GRU: A-fragments pipelined one chunk ahead ----------------
__global__ void __launch_bounds__(RNT, 1) k_recur_mma(const float* __restrict__ bih_f,
                                                      const float* __restrict__ bih_b,
                                                      const float* __restrict__ bhh_f,
                                                      const float* __restrict__ bhh_b,
                                                      float* __restrict__ out) {
    extern __shared__ char smem[];
    float*           Dsm  = (float*)(smem + SM_D);
    uint32_t*        hs32 = (uint32_t*)(smem + SM_HS);
    __nv_bfloat16*   hsb  = (__nv_bfloat16*)(smem + SM_HS);
    float*           hf   = (float*)(smem + SM_HF);
    float*           sbhh = (float*)(smem + SM_BH);
    float*           sbih = (float*)(smem + SM_BI);
    int*             sst  = (int*)(smem + SM_MISC);
    int*             sln  = sst + RBT;

    const int tid = threadIdx.x, lane = tid & 31, wid = tid >> 5;
    const int dir = blockIdx.y;
    const int b0 = blockIdx.x * RBT;
    const int wrow0 = wid * 80;
    const uint32_t swb = smem_u32(smem);

    uint32_t afro[5];
    {
        int lsel = lane >> 3, lrow = lane & 7;
        int half = lsel >> 1;
#pragma unroll
        for (int i = 0; i < 5; ++i) {
            int row = wrow0 + i * 16 + lrow + ((lsel & 1) << 3);
            afro[i] = row * 32 + ((half ^ ((row >> 2) & 1)) << 4);
        }
    }

    const __nv_bfloat16* __restrict__ gw = g_gwr + (size_t)dir * RKC * RROWS * 16;
    const float* __restrict__ xg = g_xg[dir];

#define ISSUE_WCHUNK(pfc, stg) do {                                                 \
    const char* _src = (const char*)(gw + (size_t)(pfc) * (RROWS * 16)) + wrow0 * 32; \
    _Pragma("unroll")                                                               \
    for (int _i = 0; _i < 5; ++_i) {                                                \
        int _fl = lane + 32 * _i;                                                   \
        int _row = _fl >> 1, _half = _fl & 1;                                       \
        int _ar = wrow0 + _row;                                                     \
        int _hsw = _half ^ ((_ar >> 2) & 1);                                        \
        uint32_t _d = swb + (stg) * WSTG + _ar * 32 + (_hsw << 4);                  \
        const void* _s = _src + _row * 32 + _half * 16;                             \
        asm volatile("cp.async.cg.shared.global [%0], [%1], 16;" :: "r"(_d), "l"(_s)); \
    }                                                                               \
    asm volatile("cp.async.commit_group;" ::: "memory");                            \
} while (0)

#define LDM_A(dst, stg) do {                                                        \
    uint32_t _wb = swb + (uint32_t)(stg) * WSTG;                                    \
    _Pragma("unroll")                                                               \
    for (int _i = 0; _i < 5; ++_i) {                                                \
        asm volatile("ldmatrix.sync.aligned.m8n8.x4.shared.b16 "                    \
                     "{%0,%1,%2,%3}, [%4];"                                         \
                     : "=r"((dst)[_i][0]), "=r"((dst)[_i][1]),                      \
                       "=r"((dst)[_i][2]), "=r"((dst)[_i][3])                       \
                     : "r"(_wb + afro[_i]));                                        \
    }                                                                               \
} while (0)

#define MMA_ACC(ac, Af, B0, B1)                                                     \
    asm volatile("mma.sync.aligned.m16n8k16.row.col.f32.bf16.bf16.f32 "             \
        "{%0,%1,%2,%3}, {%4,%5,%6,%7}, {%8,%9}, {%0,%1,%2,%3};"                     \
        : "+f"((ac)[0]), "+f"((ac)[1]), "+f"((ac)[2]), "+f"((ac)[3])                \
        : "r"((Af)[0]), "r"((Af)[1]), "r"((Af)[2]), "r"((Af)[3]), "r"(B0), "r"(B1))

#pragma unroll
    for (int p = 0; p < 4; ++p) ISSUE_WCHUNK(p, p);

    if (tid < RBT) { sst[tid] = g_sstart[b0 + tid]; sln[tid] = g_slen[b0 + tid]; }
    for (int i = tid; i < RBT * (HSS / 2); i += RNT) hs32[i] = 0u;
    {
        const float* bhh = dir ? bhh_b : bhh_f;
        const float* bih = dir ? bih_b : bih_f;
        for (int i = tid; i < G; i += RNT) { sbhh[i] = bhh[i]; sbih[i] = bih[i]; }
    }
    __syncthreads();
    for (int it = tid; it < RBT * H; it += RNT) {
        int j = it >> 4, b = it & 15;
        float v = g_h0[(b0 + b) * H + j];
        hf[b * HFS + j] = v;
        __nv_bfloat16 hi = __float2bfloat16(v);
        hsb[b * HSS + j] = hi;
        hsb[b * HSS + 320 + j] = __float2bfloat16(v - __bfloat162float(hi));
    }
    __syncthreads();

    // A-fragment double buffer, pipelined one chunk ahead (stream pos p = 38*s+kc,
    // stage = p&3, buffer = kc&1).
    uint32_t Afr[2][5][4];
    asm volatile("cp.async.wait_group 3;" ::: "memory");
    LDM_A(Afr[0], 0);

    for (int s = 0; s < LSEQ; ++s) {
        int t = dir ? (LSEQ - 1 - s) : s;
        float acc[5][2][4];
#pragma unroll
        for (int i = 0; i < 5; ++i)
#pragma unroll
            for (int nt = 0; nt < 2; ++nt)
#pragma unroll
                for (int e = 0; e < 4; ++e) acc[i][nt][e] = 0.f;

        const int sbase = 2 * (s & 1);

        // ---- hi chunks 0..18: W_hi x (h_hi + h_lo) ----
#pragma unroll 2
        for (int kc = 0; kc < 19; ++kc) {
            asm volatile("cp.async.wait_group 2;" ::: "memory");   // chunk kc+1 landed
            LDM_A(Afr[(kc + 1) & 1], (kc + 1 + sbase) & 3);
            const int hk = kc * 8;
            uint32_t bh[2][2], bl[2][2];
#pragma unroll
            for (int nt = 0; nt < 2; ++nt) {
                int rb = (nt * 8 + (lane >> 2)) * (HSS / 2);
                bh[nt][0] = hs32[rb + hk + (lane & 3)];
                bh[nt][1] = hs32[rb + hk + 4 + (lane & 3)];
                bl[nt][0] = hs32[rb + 160 + hk + (lane & 3)];
                bl[nt][1] = hs32[rb + 160 + hk + 4 + (lane & 3)];
            }
#pragma unroll
            for (int i = 0; i < 5; ++i)
#pragma unroll
                for (int nt = 0; nt < 2; ++nt)
                    MMA_ACC(acc[i][nt], Afr[kc & 1][i], bh[nt][0], bh[nt][1]);
#pragma unroll
            for (int i = 0; i < 5; ++i)
#pragma unroll
                for (int nt = 0; nt < 2; ++nt)
                    MMA_ACC(acc[i][nt], Afr[kc & 1][i], bl[nt][0], bl[nt][1]);
            int pfc = kc + 4; if (pfc >= RKC) pfc -= RKC;
            ISSUE_WCHUNK(pfc, (kc + sbase) & 3);
        }
        // ---- lo chunks 19..37: W_lo x h_hi ----
#pragma unroll 2
        for (int kc = 19; kc < RKC; ++kc) {
            asm volatile("cp.async.wait_group 2;" ::: "memory");
            LDM_A(Afr[(kc + 1) & 1], (kc + 1 + sbase) & 3);
            const int hk = (kc - 19) * 8;
            uint32_t bh[2][2];
#pragma unroll
            for (int nt = 0; nt < 2; ++nt) {
                int rb = (nt * 8 + (lane >> 2)) * (HSS / 2);
                bh[nt][0] = hs32[rb + hk + (lane & 3)];
                bh[nt][1] = hs32[rb + hk + 4 + (lane & 3)];
            }
#pragma unroll
            for (int i = 0; i < 5; ++i)
#pragma unroll
                for (int nt = 0; nt < 2; ++nt)
                    MMA_ACC(acc[i][nt], Afr[kc & 1][i], bh[nt][0], bh[nt][1]);
            int pfc = kc + 4; if (pfc >= RKC) pfc -= RKC;
            ISSUE_WCHUNK(pfc, (kc + sbase) & 3);
        }

#pragma unroll
        for (int i = 0; i < 5; ++i) {
            int r0 = wrow0 + i * 16 + (lane >> 2);
#pragma unroll
            for (int nt = 0; nt < 2; ++nt) {
                int c = nt * 8 + (lane & 3) * 2;
                *(float2*)(Dsm + r0 * 16 + c) = make_float2(acc[i][nt][0], acc[i][nt][1]);
                *(float2*)(Dsm + (r0 + 8) * 16 + c) = make_float2(acc[i][nt][2], acc[i][nt][3]);
            }
        }
        __syncthreads();

        for (int it = tid; it < RBT * H; it += RNT) {
            int j = it >> 4, b = it & 15;
            bool valid = t < sln[b];
            size_t ni = (size_t)(sst[b] + t);
            float x0, x1, x2;
            if (valid) {
                const float* xr = xg + ni * G;
                x0 = ldcs(xr + j); x1 = ldcs(xr + H + j); x2 = ldcs(xr + 2 * H + j);
            } else {
                x0 = sbih[j]; x1 = sbih[H + j]; x2 = sbih[2 * H + j];
            }
            float hgr = Dsm[j * 16 + b];
            float hgz = Dsm[(GP + j) * 16 + b];
            float hgn = Dsm[(2 * GP + j) * 16 + b];
            float r  = sigm(x0 + hgr + sbhh[j]);
            float z  = sigm(x1 + hgz + sbhh[H + j]);
            float nn = tanh_fast(x2 + r * (hgn + sbhh[2 * H + j]));
            float hp = hf[b * HFS + j];
            float hv = (1.f - z) * nn + z * hp;
            hf[b * HFS + j] = hv;
            __nv_bfloat16 hi = __float2bfloat16(hv);
            hsb[b * HSS + j] = hi;
            hsb[b * HSS + 320 + j] = __float2bfloat16(hv - __bfloat162float(hi));
            if (valid) stcs(out + ni * (2 * H) + dir * H + j, hv);
        }
        __syncthreads();
    }
    asm volatile("cp.async.wait_group 0;" ::: "memory");
#undef ISSUE_WCHUNK
#undef LDM_A
#undef MMA_ACC
}

// ---------------- host entry ----------------
extern "C" void kernel_launch(void* const* d_in, const int* in_sizes, int n_in,
                              void* d_out, int out_size) {
    const float* node   = (const float*)d_in[0];
    const int*   batch  = (const int*)d_in[1];
    const int*   pos    = (const int*)d_in[2];
    const float* bias   = (const float*)d_in[3];
    const float* w_ih_f = (const float*)d_in[4];
    const float* w_hh_f = (const float*)d_in[5];
    const float* b_ih_f = (const float*)d_in[6];
    const float* b_hh_f = (const float*)d_in[7];
    const float* w_ih_b = (const float*)d_in[8];
    const float* w_hh_b = (const float*)d_in[9];
    const float* b_ih_b = (const float*)d_in[10];
    const float* b_hh_b = (const float*)d_in[11];
    float* out = (float*)d_out;
    int n = in_sizes[0] / H;

    cudaFuncSetAttribute(k_gemm_mma, cudaFuncAttributeMaxDynamicSharedMemorySize, GSM_TOT);
    cudaFuncSetAttribute(k_recur_mma, cudaFuncAttributeMaxDynamicSharedMemorySize, SM_TOT);

    int gprep = 64 + n + 512 + 256;
    k_prep<<<gprep, 256>>>(node, bias, batch, pos, w_ih_f, w_ih_b, w_hh_f, w_hh_b, n);
    k_h0<<<NB, NTHREADS>>>(node);
    k_gemm_mma<<<dim3(16, n / MT), 256, GSM_TOT>>>(b_ih_f, b_ih_b);
    k_recur_mma<<<dim3(NB / RBT, 2), RNT, SM_TOT>>>(b_ih_f, b_ih_b, b_hh_f, b_hh_b, out);
}

// round 11
// speedup vs baseline: 2.1901x; 1.0135x over previous
#include <cuda_runtime.h>
#include <cuda_bf16.h>
#include <math.h>
#include <cstdint>

#define H     300
#define G     900
#define NB    1024
#define LSEQ  64
#define NTHREADS 320
#define NNODES 49152

// ---- input GEMM config ----
#define KP  960
#define NP  1024
#define MT  128
#define NKB2 (KP / 32)
#define SROW 80
#define GSTG 20480
#define GSM_TOT (3 * GSTG)

// ---- recurrent mma config ----
#define GP    304                  // rows per gate (19 m16 tiles)
#define RROWS 912                  // 3*GP, 57 m16 tiles
#define RKC   38                   // 19 hi + 19 lo k16 chunks
#define WSTG  (RROWS * 32)         // ring stage: 29184 B
#define HSS   648                  // h-split row stride (bf16)
#define HFS   304
#define RBT   16                   // graphs per CTA
#define RNT   512                  // 16 warps

// dynamic smem layout (bytes)
#define SM_W    0
#define SM_D    (4 * WSTG)                    // 116736
#define SM_HS   (SM_D + RROWS * 16 * 4)       // 175104
#define SM_HF   (SM_HS + RBT * HSS * 2)       // 195840
#define SM_BH   (SM_HF + RBT * HFS * 4)       // 215296
#define SM_BI   (SM_BH + 3600)                // 218896
#define SM_MISC (SM_BI + 3600)                // 222496
#define SM_TOT  (SM_MISC + 128)               // 222624

__device__ __forceinline__ float sigm(float x) { return 1.f / (1.f + __expf(-x)); }
__device__ __forceinline__ float tanh_fast(float x) {
    float s = 1.f / (1.f + __expf(-2.f * x));
    return 2.f * s - 1.f;
}
__device__ __forceinline__ uint32_t smem_u32(const void* p) {
    uint32_t a;
    asm("{ .reg .u64 t; cvta.to.shared.u64 t, %1; cvt.u32.u64 %0, t; }" : "=r"(a) : "l"(p));
    return a;
}
__device__ __forceinline__ float ldcs(const float* p) {
    float v; asm volatile("ld.global.cs.f32 %0, [%1];" : "=f"(v) : "l"(p)); return v;
}
__device__ __forceinline__ void stcs(float* p, float v) {
    asm volatile("st.global.cs.f32 [%0], %1;" :: "l"(p), "f"(v));
}

// ---------------- device scratch ----------------
__device__ __align__(16) __nv_bfloat16 g_abf[(size_t)NNODES * KP];
__device__ __align__(16) __nv_bfloat16 g_bbf[2][(size_t)NP * KP];
__device__ __align__(16) __nv_bfloat16 g_gwr[(size_t)2 * RKC * RROWS * 16];
__device__ float g_xg[2][(size_t)NNODES * G];
__device__ float g_h0[NB * H];
__device__ int   g_sstart[NB];
__device__ int   g_slen[NB];

// ---------------- 1) merged prep: seg | convA | convB | convW ----------------
__global__ void __launch_bounds__(256) k_prep(const float* __restrict__ node,
                                              const float* __restrict__ bias,
                                              const int* __restrict__ batch,
                                              const int* __restrict__ pos,
                                              const float* __restrict__ wif,
                                              const float* __restrict__ wib,
                                              const float* __restrict__ whf,
                                              const float* __restrict__ whb,
                                              int n) {
    __shared__ float sb[H];
    const int bx = blockIdx.x, tid = threadIdx.x;
    if (bx < 64) {
        for (int i = bx * 256 + tid; i < n; i += 64 * 256) {
            int b = batch[i];
            if (pos[i] == 0) g_sstart[b] = i;
            if (i == n - 1 || batch[i + 1] != b) g_slen[b] = pos[i] + 1;
        }
    } else if (bx < 64 + n) {
        int i = bx - 64;
        for (int k = tid; k < H; k += 256) {
            float v = node[(size_t)i * H + k] + bias[k];
            sb[k] = v > 0.f ? v : 0.f;
        }
        __syncthreads();
        __nv_bfloat16* dst = g_abf + (size_t)i * KP;
        for (int kp = tid; kp < KP; kp += 256) {
            __nv_bfloat16 o = __float2bfloat16(0.f);
            int k = -1; bool lo = false;
            if (kp < 300)                    { k = kp; }
            else if (kp >= 320 && kp < 620)  { k = kp - 320; lo = true; }
            else if (kp >= 640 && kp < 940)  { k = kp - 640; }
            if (k >= 0) {
                float m = sb[k];
                __nv_bfloat16 hi = __float2bfloat16(m);
                o = lo ? __float2bfloat16(m - __bfloat162float(hi)) : hi;
            }
            dst[kp] = o;
        }
    } else if (bx < 64 + n + 512) {
        size_t tot = (size_t)2 * NP * KP;
        int bb = bx - 64 - n;
        for (size_t idx = (size_t)bb * 256 + tid; idx < tot; idx += (size_t)512 * 256) {
            int dir = (int)(idx / ((size_t)NP * KP));
            size_t r = idx - (size_t)dir * NP * KP;
            int g = (int)(r / KP), kp = (int)(r - (size_t)g * KP);
            __nv_bfloat16 o = __float2bfloat16(0.f);
            int k = -1; bool lo = false;
            if (kp < 300)                    { k = kp; }
            else if (kp >= 320 && kp < 620)  { k = kp - 320; }
            else if (kp >= 640 && kp < 940)  { k = kp - 640; lo = true; }
            if (k >= 0 && g < G) {
                const float* w = dir ? wib : wif;
                float v = w[(size_t)g * H + k];
                __nv_bfloat16 hi = __float2bfloat16(v);
                o = lo ? __float2bfloat16(v - __bfloat162float(hi)) : hi;
            }
            g_bbf[dir][r] = o;
        }
    } else {
        const int tot = 2 * RKC * RROWS * 16;
        int bb = bx - 64 - n - 512;
        for (int idx = bb * 256 + tid; idx < tot; idx += 256 * 256) {
            int dir = idx / (RKC * RROWS * 16);
            int r = idx % (RKC * RROWS * 16);
            int kc = r / (RROWS * 16);
            int rr = r % (RROWS * 16);
            int row = rr >> 4, c = rr & 15;
            int gate = row / GP, j = row % GP;
            bool lo = kc >= 19;
            int k = (lo ? kc - 19 : kc) * 16 + c;
            __nv_bfloat16 o = __float2bfloat16(0.f);
            if (j < H && k < H) {
                const float* w = dir ? whb : whf;
                float v = w[(size_t)(gate * H + j) * H + k];
                __nv_bfloat16 hi = __float2bfloat16(v);
                o = lo ? __float2bfloat16(v - __bfloat162float(hi)) : hi;
            }
            g_gwr[idx] = o;
        }
    }
}

// ---------------- 2) h0 = per-graph segment max ----------------
__global__ void __launch_bounds__(NTHREADS) k_h0(const float* __restrict__ node) {
    int b = blockIdx.x, h = threadIdx.x;
    if (h >= H) return;
    int s = g_sstart[b], l = g_slen[b];
    float m = -3.402823466e38f;
    for (int i = 0; i < l; ++i) m = fmaxf(m, node[(size_t)(s + i) * H + h]);
    g_h0[b * H + h] = m;
}

// ---------------- 3) input GEMM (proven round-8) ----------------
__global__ void __launch_bounds__(256, 2) k_gemm_mma(const float* __restrict__ bih_f,
                                                     const float* __restrict__ bih_b) {
    extern __shared__ unsigned char gsm[];
    const int tid = threadIdx.x, lane = tid & 31, wid = tid >> 5;
    const int dir = blockIdx.x >> 3, ntile = blockIdx.x & 7;
    const int m0 = blockIdx.y * MT, n0 = ntile * 128;
    const int wm = wid & 3, wn = wid >> 2;

    const __nv_bfloat16* __restrict__ A = g_abf + (size_t)m0 * KP;
    const __nv_bfloat16* __restrict__ B = g_bbf[dir] + (size_t)n0 * KP;
    const uint32_t s0 = smem_u32(gsm);

    float d[2][8][4];
#pragma unroll
    for (int mi = 0; mi < 2; ++mi)
#pragma unroll
        for (int ni = 0; ni < 8; ++ni)
#pragma unroll
            for (int e = 0; e < 4; ++e) d[mi][ni][e] = 0.f;

#define ISSUE_STAGE(kb, stg) do {                                                   \
    _Pragma("unroll")                                                               \
    for (int _p = 0; _p < 2; ++_p) {                                                \
        int _u = _p * 256 + tid, _row = _u >> 2, _c = _u & 3;                       \
        const void* _ga = A + (size_t)_row * KP + (kb) * 32 + _c * 8;               \
        uint32_t _da = s0 + (stg) * GSTG + _row * SROW + _c * 16;                   \
        asm volatile("cp.async.cg.shared.global [%0], [%1], 16;" :: "r"(_da), "l"(_ga)); \
        const void* _gb = B + (size_t)_row * KP + (kb) * 32 + _c * 8;               \
        uint32_t _db = s0 + (stg) * GSTG + 10240 + _row * SROW + _c * 16;           \
        asm volatile("cp.async.cg.shared.global [%0], [%1], 16;" :: "r"(_db), "l"(_gb)); \
    }                                                                               \
    asm volatile("cp.async.commit_group;" ::: "memory");                            \
} while (0)

#define GEMM_COMPUTE(a32, b32, NIMAX)                                               \
    _Pragma("unroll")                                                               \
    for (int ks = 0; ks < 2; ++ks) {                                                \
        uint32_t af[2][4];                                                          \
        _Pragma("unroll")                                                           \
        for (int mi = 0; mi < 2; ++mi) {                                            \
            int r0 = wm * 32 + mi * 16 + (lane >> 2);                               \
            af[mi][0] = (a32)[r0 * 20 + ks * 8 + (lane & 3)];                       \
            af[mi][1] = (a32)[(r0 + 8) * 20 + ks * 8 + (lane & 3)];                 \
            af[mi][2] = (a32)[r0 * 20 + ks * 8 + 4 + (lane & 3)];                   \
            af[mi][3] = (a32)[(r0 + 8) * 20 + ks * 8 + 4 + (lane & 3)];             \
        }                                                                           \
        _Pragma("unroll")                                                           \
        for (int ni = 0; ni < (NIMAX); ++ni) {                                      \
            int cn = wn * 64 + ni * 8 + (lane >> 2);                                \
            uint32_t b0 = (b32)[cn * 20 + ks * 8 + (lane & 3)];                     \
            uint32_t b1 = (b32)[cn * 20 + ks * 8 + 4 + (lane & 3)];                 \
            _Pragma("unroll")                                                       \
            for (int mi = 0; mi < 2; ++mi) {                                        \
                asm volatile(                                                       \
                    "mma.sync.aligned.m16n8k16.row.col.f32.bf16.bf16.f32 "          \
                    "{%0,%1,%2,%3}, {%4,%5,%6,%7}, {%8,%9}, {%0,%1,%2,%3};"         \
                    : "+f"(d[mi][ni][0]), "+f"(d[mi][ni][1]),                       \
                      "+f"(d[mi][ni][2]), "+f"(d[mi][ni][3])                        \
                    : "r"(af[mi][0]), "r"(af[mi][1]), "r"(af[mi][2]), "r"(af[mi][3]), \
                      "r"(b0), "r"(b1));                                            \
            }                                                                       \
        }                                                                           \
    }

    ISSUE_STAGE(0, 0);
    ISSUE_STAGE(1, 1);
    const bool tail = (ntile == 7);
    int stg = 0;
    for (int kb = 0; kb < NKB2; ++kb) {
        if (kb <= NKB2 - 2) { asm volatile("cp.async.wait_group 1;" ::: "memory"); }
        else                { asm volatile("cp.async.wait_group 0;" ::: "memory"); }
        __syncthreads();
        const uint32_t* a32 = (const uint32_t*)(gsm + stg * GSTG);
        const uint32_t* b32 = (const uint32_t*)(gsm + stg * GSTG + 10240);
        if (!tail) { GEMM_COMPUTE(a32, b32, 8); }
        else       { GEMM_COMPUTE(a32, b32, 1); }
        if (kb + 2 < NKB2) {
            int ns = stg + 2; if (ns >= 3) ns -= 3;
            ISSUE_STAGE(kb + 2, ns);
        }
        if (++stg == 3) stg = 0;
    }
#undef ISSUE_STAGE
#undef GEMM_COMPUTE

    const float* __restrict__ bih = dir ? bih_b : bih_f;
    float* __restrict__ xg = g_xg[dir];
    const int nimax = tail ? 1 : 8;
#pragma unroll
    for (int mi = 0; mi < 2; ++mi) {
        int r0 = m0 + wm * 32 + mi * 16 + (lane >> 2);
        for (int ni = 0; ni < nimax; ++ni) {
            int g = n0 + wn * 64 + ni * 8 + (lane & 3) * 2;
            if (g < G) {
                float bg0 = bih[g], bg1 = bih[g + 1];
                *(float2*)(xg + (size_t)r0 * G + g) =
                    make_float2(d[mi][ni][0] + bg0, d[mi][ni][1] + bg1);
                *(float2*)(xg + (size_t)(r0 + 8) * G + g) =
                    make_float2(d[mi][ni][2] + bg0, d[mi][ni][3] + bg1);
            }
        }
    }
}

// ---------------- 4) recurrent GRU: 16 warps, trimmed padding ----------------
__global__ void __launch_bounds__(RNT, 1) k_recur_mma(const float* __restrict__ bih_f,
                                                      const float* __restrict__ bih_b,
                                                      const float* __restrict__ bhh_f,
                                                      const float* __restrict__ bhh_b,
                                                      float* __restrict__ out) {
    extern __shared__ char smem[];
    float*           Dsm  = (float*)(smem + SM_D);
    uint32_t*        hs32 = (uint32_t*)(smem + SM_HS);
    __nv_bfloat16*   hsb  = (__nv_bfloat16*)(smem + SM_HS);
    float*           hf   = (float*)(smem + SM_HF);
    float*           sbhh = (float*)(smem + SM_BH);
    float*           sbih = (float*)(smem + SM_BI);
    int*             sst  = (int*)(smem + SM_MISC);
    int*             sln  = sst + RBT;

    const int tid = threadIdx.x, lane = tid & 31, wid = tid >> 5;
    const int dir = blockIdx.y;
    const int b0 = blockIdx.x * RBT;
    // uneven warp tiling: warps 0-8 own 4 m16 tiles, warps 9-15 own 3 (57 total)
    const int ntl   = (wid < 9) ? 4 : 3;
    const int wrow0 = (wid < 9) ? wid * 64 : 576 + (wid - 9) * 48;
    const uint32_t swb = smem_u32(smem);

    uint32_t afro[4];
    {
        int lsel = lane >> 3, lrow = lane & 7;
        int half = lsel >> 1;
#pragma unroll
        for (int i = 0; i < 4; ++i) {
            int row = wrow0 + i * 16 + lrow + ((lsel & 1) << 3);
            afro[i] = row * 32 + ((half ^ ((row >> 2) & 1)) << 4);
        }
    }

    const __nv_bfloat16* __restrict__ gw = g_gwr + (size_t)dir * RKC * RROWS * 16;
    const float* __restrict__ xg = g_xg[dir];

    // per-warp chunk issue: ntl*16 rows x 32B (2 halves per row)
#define ISSUE_WCHUNK(pfc, stg) do {                                                 \
    const char* _src = (const char*)(gw + (size_t)(pfc) * (RROWS * 16)) + wrow0 * 32; \
    const int _nt2 = ntl * 32;                                                      \
    _Pragma("unroll")                                                               \
    for (int _i = 0; _i < 4; ++_i) {                                                \
        int _fl = lane + 32 * _i;                                                   \
        if (_fl < _nt2) {                                                           \
            int _row = _fl >> 1, _half = _fl & 1;                                   \
            int _ar = wrow0 + _row;                                                 \
            int _hsw = _half ^ ((_ar >> 2) & 1);                                    \
            uint32_t _d = swb + (stg) * WSTG + _ar * 32 + (_hsw << 4);              \
            const void* _s = _src + _row * 32 + _half * 16;                         \
            asm volatile("cp.async.cg.shared.global [%0], [%1], 16;" :: "r"(_d), "l"(_s)); \
        }                                                                           \
    }                                                                               \
    asm volatile("cp.async.commit_group;" ::: "memory");                            \
} while (0)

#define MMA_ACC(ac, Af, B0, B1)                                                     \
    asm volatile("mma.sync.aligned.m16n8k16.row.col.f32.bf16.bf16.f32 "             \
        "{%0,%1,%2,%3}, {%4,%5,%6,%7}, {%8,%9}, {%0,%1,%2,%3};"                     \
        : "+f"((ac)[0]), "+f"((ac)[1]), "+f"((ac)[2]), "+f"((ac)[3])                \
        : "r"((Af)[0]), "r"((Af)[1]), "r"((Af)[2]), "r"((Af)[3]), "r"(B0), "r"(B1))

#pragma unroll
    for (int p = 0; p < 4; ++p) ISSUE_WCHUNK(p, p);

    if (tid < RBT) { sst[tid] = g_sstart[b0 + tid]; sln[tid] = g_slen[b0 + tid]; }
    for (int i = tid; i < RBT * (HSS / 2); i += RNT) hs32[i] = 0u;
    {
        const float* bhh = dir ? bhh_b : bhh_f;
        const float* bih = dir ? bih_b : bih_f;
        for (int i = tid; i < G; i += RNT) { sbhh[i] = bhh[i]; sbih[i] = bih[i]; }
    }
    __syncthreads();
    for (int it = tid; it < RBT * H; it += RNT) {
        int j = it >> 4, b = it & 15;
        float v = g_h0[(b0 + b) * H + j];
        hf[b * HFS + j] = v;
        __nv_bfloat16 hi = __float2bfloat16(v);
        hsb[b * HSS + j] = hi;
        hsb[b * HSS + 320 + j] = __float2bfloat16(v - __bfloat162float(hi));
    }
    __syncthreads();

    for (int s = 0; s < LSEQ; ++s) {
        int t = dir ? (LSEQ - 1 - s) : s;
        float acc[4][2][4];
#pragma unroll
        for (int i = 0; i < 4; ++i)
#pragma unroll
            for (int nt = 0; nt < 2; ++nt)
#pragma unroll
                for (int e = 0; e < 4; ++e) acc[i][nt][e] = 0.f;

        const int sbase = 2 * (s & 1);          // (38*s) mod 4

        // ---- hi chunks 0..18: W_hi x (h_hi + h_lo) ----
#pragma unroll 1
        for (int kc = 0; kc < 19; ++kc) {
            const int stage = (kc + sbase) & 3;
            asm volatile("cp.async.wait_group 3;" ::: "memory");
            const uint32_t wbase = swb + (uint32_t)stage * WSTG;
            const int hk = kc * 8;
            uint32_t A[4][4];
            for (int i = 0; i < ntl; ++i) {
                asm volatile("ldmatrix.sync.aligned.m8n8.x4.shared.b16 "
                             "{%0,%1,%2,%3}, [%4];"
                             : "=r"(A[i][0]), "=r"(A[i][1]), "=r"(A[i][2]), "=r"(A[i][3])
                             : "r"(wbase + afro[i]));
            }
            uint32_t bh[2][2], bl[2][2];
#pragma unroll
            for (int nt = 0; nt < 2; ++nt) {
                int rb = (nt * 8 + (lane >> 2)) * (HSS / 2);
                bh[nt][0] = hs32[rb + hk + (lane & 3)];
                bh[nt][1] = hs32[rb + hk + 4 + (lane & 3)];
                bl[nt][0] = hs32[rb + 160 + hk + (lane & 3)];
                bl[nt][1] = hs32[rb + 160 + hk + 4 + (lane & 3)];
            }
            for (int i = 0; i < ntl; ++i) {
#pragma unroll
                for (int nt = 0; nt < 2; ++nt)
                    MMA_ACC(acc[i][nt], A[i], bh[nt][0], bh[nt][1]);
            }
            for (int i = 0; i < ntl; ++i) {
#pragma unroll
                for (int nt = 0; nt < 2; ++nt)
                    MMA_ACC(acc[i][nt], A[i], bl[nt][0], bl[nt][1]);
            }
            int pfc = kc + 4; if (pfc >= RKC) pfc -= RKC;
            ISSUE_WCHUNK(pfc, stage);
        }
        // ---- lo chunks 19..37: W_lo x h_hi ----
#pragma unroll 1
        for (int kc = 19; kc < RKC; ++kc) {
            const int stage = (kc + sbase) & 3;
            asm volatile("cp.async.wait_group 3;" ::: "memory");
            const uint32_t wbase = swb + (uint32_t)stage * WSTG;
            const int hk = (kc - 19) * 8;
            uint32_t A[4][4];
            for (int i = 0; i < ntl; ++i) {
                asm volatile("ldmatrix.sync.aligned.m8n8.x4.shared.b16 "
                             "{%0,%1,%2,%3}, [%4];"
                             : "=r"(A[i][0]), "=r"(A[i][1]), "=r"(A[i][2]), "=r"(A[i][3])
                             : "r"(wbase + afro[i]));
            }
            uint32_t bh[2][2];
#pragma unroll
            for (int nt = 0; nt < 2; ++nt) {
                int rb = (nt * 8 + (lane >> 2)) * (HSS / 2);
                bh[nt][0] = hs32[rb + hk + (lane & 3)];
                bh[nt][1] = hs32[rb + hk + 4 + (lane & 3)];
            }
            for (int i = 0; i < ntl; ++i) {
#pragma unroll
                for (int nt = 0; nt < 2; ++nt)
                    MMA_ACC(acc[i][nt], A[i], bh[nt][0], bh[nt][1]);
            }
            int pfc = kc + 4; if (pfc >= RKC) pfc -= RKC;
            ISSUE_WCHUNK(pfc, stage);
        }

        // write hg preactivations D[row][graph]
        for (int i = 0; i < ntl; ++i) {
            int r0 = wrow0 + i * 16 + (lane >> 2);
#pragma unroll
            for (int nt = 0; nt < 2; ++nt) {
                int c = nt * 8 + (lane & 3) * 2;
                *(float2*)(Dsm + r0 * 16 + c) = make_float2(acc[i][nt][0], acc[i][nt][1]);
                *(float2*)(Dsm + (r0 + 8) * 16 + c) = make_float2(acc[i][nt][2], acc[i][nt][3]);
            }
        }
        __syncthreads();

        // pointwise GRU update
        for (int it = tid; it < RBT * H; it += RNT) {
            int j = it >> 4, b = it & 15;
            bool valid = t < sln[b];
            size_t ni = (size_t)(sst[b] + t);
            float x0, x1, x2;
            if (valid) {
                const float* xr = xg + ni * G;
                x0 = ldcs(xr + j); x1 = ldcs(xr + H + j); x2 = ldcs(xr + 2 * H + j);
            } else {
                x0 = sbih[j]; x1 = sbih[H + j]; x2 = sbih[2 * H + j];
            }
            float hgr = Dsm[j * 16 + b];
            float hgz = Dsm[(GP + j) * 16 + b];
            float hgn = Dsm[(2 * GP + j) * 16 + b];
            float r  = sigm(x0 + hgr + sbhh[j]);
            float z  = sigm(x1 + hgz + sbhh[H + j]);
            float nn = tanh_fast(x2 + r * (hgn + sbhh[2 * H + j]));
            float hp = hf[b * HFS + j];
            float hv = (1.f - z) * nn + z * hp;
            hf[b * HFS + j] = hv;
            __nv_bfloat16 hi = __float2bfloat16(hv);
            hsb[b * HSS + j] = hi;
            hsb[b * HSS + 320 + j] = __float2bfloat16(hv - __bfloat162float(hi));
            if (valid) stcs(out + ni * (2 * H) + dir * H + j, hv);
        }
        __syncthreads();
    }
    asm volatile("cp.async.wait_group 0;" ::: "memory");
#undef ISSUE_WCHUNK
#undef MMA_ACC
}

// ---------------- host entry ----------------
extern "C" void kernel_launch(void* const* d_in, const int* in_sizes, int n_in,
                              void* d_out, int out_size) {
    const float* node   = (const float*)d_in[0];
    const int*   batch  = (const int*)d_in[1];
    const int*   pos    = (const int*)d_in[2];
    const float* bias   = (const float*)d_in[3];
    const float* w_ih_f = (const float*)d_in[4];
    const float* w_hh_f = (const float*)d_in[5];
    const float* b_ih_f = (const float*)d_in[6];
    const float* b_hh_f = (const float*)d_in[7];
    const float* w_ih_b = (const float*)d_in[8];
    const float* w_hh_b = (const float*)d_in[9];
    const float* b_ih_b = (const float*)d_in[10];
    const float* b_hh_b = (const float*)d_in[11];
    float* out = (float*)d_out;
    int n = in_sizes[0] / H;

    cudaFuncSetAttribute(k_gemm_mma, cudaFuncAttributeMaxDynamicSharedMemorySize, GSM_TOT);
    cudaFuncSetAttribute(k_recur_mma, cudaFuncAttributeMaxDynamicSharedMemorySize, SM_TOT);

    int gprep = 64 + n + 512 + 256;
    k_prep<<<gprep, 256>>>(node, bias, batch, pos, w_ih_f, w_ih_b, w_hh_f, w_hh_b, n);
    k_h0<<<NB, NTHREADS>>>(node);
    k_gemm_mma<<<dim3(16, n / MT), 256, GSM_TOT>>>(b_ih_f, b_ih_b);
    k_recur_mma<<<dim3(NB / RBT, 2), RNT, SM_TOT>>>(b_ih_f, b_ih_b, b_hh_f, b_hh_b, out);
}

// round 12
// speedup vs baseline: 2.2345x; 1.0203x over previous
#include <cuda_runtime.h>
#include <cuda_bf16.h>
#include <math.h>
#include <cstdint>

#define H     300
#define G     900
#define NB    1024
#define LSEQ  64
#define NTHREADS 320
#define NNODES 49152

// ---- input GEMM config ----
#define KP  960
#define NP  1024
#define MT  128
#define NKB2 (KP / 32)
#define SROW 80
#define GSTG 20480
#define GSM_TOT (3 * GSTG)

// ---- recurrent mma config ----
#define GP    304                  // rows per gate (19 m16 tiles)
#define RROWS 912                  // 3*GP, 57 m16 tiles
#define RKC   38                   // 19 hi + 19 lo k16 chunks
#define WSTG  (RROWS * 32)         // ring stage: 29184 B
#define HSS   648                  // h-split row stride (bf16)
#define HFS   304
#define RBT   16                   // graphs per CTA
#define RNT   512                  // 16 warps
#define PWIT  10                   // ceil(RBT*H / RNT) pointwise items/thread

// dynamic smem layout (bytes)
#define SM_W    0
#define SM_D    (4 * WSTG)                    // 116736
#define SM_HS   (SM_D + RROWS * 16 * 4)       // 175104
#define SM_HF   (SM_HS + RBT * HSS * 2)       // 195840
#define SM_BH   (SM_HF + RBT * HFS * 4)       // 215296
#define SM_BI   (SM_BH + 3600)                // 218896
#define SM_MISC (SM_BI + 3600)                // 222496
#define SM_TOT  (SM_MISC + 128)               // 222624

__device__ __forceinline__ float sigm(float x) { return 1.f / (1.f + __expf(-x)); }
__device__ __forceinline__ float tanh_fast(float x) {
    float s = 1.f / (1.f + __expf(-2.f * x));
    return 2.f * s - 1.f;
}
__device__ __forceinline__ uint32_t smem_u32(const void* p) {
    uint32_t a;
    asm("{ .reg .u64 t; cvta.to.shared.u64 t, %1; cvt.u32.u64 %0, t; }" : "=r"(a) : "l"(p));
    return a;
}
__device__ __forceinline__ float ldcs(const float* p) {
    float v; asm volatile("ld.global.cs.f32 %0, [%1];" : "=f"(v) : "l"(p)); return v;
}
__device__ __forceinline__ void stcs(float* p, float v) {
    asm volatile("st.global.cs.f32 [%0], %1;" :: "l"(p), "f"(v));
}

// ---------------- device scratch ----------------
__device__ __align__(16) __nv_bfloat16 g_abf[(size_t)NNODES * KP];
__device__ __align__(16) __nv_bfloat16 g_bbf[2][(size_t)NP * KP];
__device__ __align__(16) __nv_bfloat16 g_gwr[(size_t)2 * RKC * RROWS * 16];
__device__ float g_xg[2][(size_t)NNODES * G];
__device__ float g_h0[NB * H];
__device__ int   g_sstart[NB];
__device__ int   g_slen[NB];

// ---------------- 1) merged prep: seg | convA | convB | convW ----------------
__global__ void __launch_bounds__(256) k_prep(const float* __restrict__ node,
                                              const float* __restrict__ bias,
                                              const int* __restrict__ batch,
                                              const int* __restrict__ pos,
                                              const float* __restrict__ wif,
                                              const float* __restrict__ wib,
                                              const float* __restrict__ whf,
                                              const float* __restrict__ whb,
                                              int n) {
    __shared__ float sb[H];
    const int bx = blockIdx.x, tid = threadIdx.x;
    if (bx < 64) {
        for (int i = bx * 256 + tid; i < n; i += 64 * 256) {
            int b = batch[i];
            if (pos[i] == 0) g_sstart[b] = i;
            if (i == n - 1 || batch[i + 1] != b) g_slen[b] = pos[i] + 1;
        }
    } else if (bx < 64 + n) {
        int i = bx - 64;
        for (int k = tid; k < H; k += 256) {
            float v = node[(size_t)i * H + k] + bias[k];
            sb[k] = v > 0.f ? v : 0.f;
        }
        __syncthreads();
        __nv_bfloat16* dst = g_abf + (size_t)i * KP;
        for (int kp = tid; kp < KP; kp += 256) {
            __nv_bfloat16 o = __float2bfloat16(0.f);
            int k = -1; bool lo = false;
            if (kp < 300)                    { k = kp; }
            else if (kp >= 320 && kp < 620)  { k = kp - 320; lo = true; }
            else if (kp >= 640 && kp < 940)  { k = kp - 640; }
            if (k >= 0) {
                float m = sb[k];
                __nv_bfloat16 hi = __float2bfloat16(m);
                o = lo ? __float2bfloat16(m - __bfloat162float(hi)) : hi;
            }
            dst[kp] = o;
        }
    } else if (bx < 64 + n + 512) {
        size_t tot = (size_t)2 * NP * KP;
        int bb = bx - 64 - n;
        for (size_t idx = (size_t)bb * 256 + tid; idx < tot; idx += (size_t)512 * 256) {
            int dir = (int)(idx / ((size_t)NP * KP));
            size_t r = idx - (size_t)dir * NP * KP;
            int g = (int)(r / KP), kp = (int)(r - (size_t)g * KP);
            __nv_bfloat16 o = __float2bfloat16(0.f);
            int k = -1; bool lo = false;
            if (kp < 300)                    { k = kp; }
            else if (kp >= 320 && kp < 620)  { k = kp - 320; }
            else if (kp >= 640 && kp < 940)  { k = kp - 640; lo = true; }
            if (k >= 0 && g < G) {
                const float* w = dir ? wib : wif;
                float v = w[(size_t)g * H + k];
                __nv_bfloat16 hi = __float2bfloat16(v);
                o = lo ? __float2bfloat16(v - __bfloat162float(hi)) : hi;
            }
            g_bbf[dir][r] = o;
        }
    } else {
        const int tot = 2 * RKC * RROWS * 16;
        int bb = bx - 64 - n - 512;
        for (int idx = bb * 256 + tid; idx < tot; idx += 256 * 256) {
            int dir = idx / (RKC * RROWS * 16);
            int r = idx % (RKC * RROWS * 16);
            int kc = r / (RROWS * 16);
            int rr = r % (RROWS * 16);
            int row = rr >> 4, c = rr & 15;
            int gate = row / GP, j = row % GP;
            bool lo = kc >= 19;
            int k = (lo ? kc - 19 : kc) * 16 + c;
            __nv_bfloat16 o = __float2bfloat16(0.f);
            if (j < H && k < H) {
                const float* w = dir ? whb : whf;
                float v = w[(size_t)(gate * H + j) * H + k];
                __nv_bfloat16 hi = __float2bfloat16(v);
                o = lo ? __float2bfloat16(v - __bfloat162float(hi)) : hi;
            }
            g_gwr[idx] = o;
        }
    }
}

// ---------------- 2) h0 = per-graph segment max ----------------
__global__ void __launch_bounds__(NTHREADS) k_h0(const float* __restrict__ node) {
    int b = blockIdx.x, h = threadIdx.x;
    if (h >= H) return;
    int s = g_sstart[b], l = g_slen[b];
    float m = -3.402823466e38f;
    for (int i = 0; i < l; ++i) m = fmaxf(m, node[(size_t)(s + i) * H + h]);
    g_h0[b * H + h] = m;
}

// ---------------- 3) input GEMM (proven round-8) ----------------
__global__ void __launch_bounds__(256, 2) k_gemm_mma(const float* __restrict__ bih_f,
                                                     const float* __restrict__ bih_b) {
    extern __shared__ unsigned char gsm[];
    const int tid = threadIdx.x, lane = tid & 31, wid = tid >> 5;
    const int dir = blockIdx.x >> 3, ntile = blockIdx.x & 7;
    const int m0 = blockIdx.y * MT, n0 = ntile * 128;
    const int wm = wid & 3, wn = wid >> 2;

    const __nv_bfloat16* __restrict__ A = g_abf + (size_t)m0 * KP;
    const __nv_bfloat16* __restrict__ B = g_bbf[dir] + (size_t)n0 * KP;
    const uint32_t s0 = smem_u32(gsm);

    float d[2][8][4];
#pragma unroll
    for (int mi = 0; mi < 2; ++mi)
#pragma unroll
        for (int ni = 0; ni < 8; ++ni)
#pragma unroll
            for (int e = 0; e < 4; ++e) d[mi][ni][e] = 0.f;

#define ISSUE_STAGE(kb, stg) do {                                                   \
    _Pragma("unroll")                                                               \
    for (int _p = 0; _p < 2; ++_p) {                                                \
        int _u = _p * 256 + tid, _row = _u >> 2, _c = _u & 3;                       \
        const void* _ga = A + (size_t)_row * KP + (kb) * 32 + _c * 8;               \
        uint32_t _da = s0 + (stg) * GSTG + _row * SROW + _c * 16;                   \
        asm volatile("cp.async.cg.shared.global [%0], [%1], 16;" :: "r"(_da), "l"(_ga)); \
        const void* _gb = B + (size_t)_row * KP + (kb) * 32 + _c * 8;               \
        uint32_t _db = s0 + (stg) * GSTG + 10240 + _row * SROW + _c * 16;           \
        asm volatile("cp.async.cg.shared.global [%0], [%1], 16;" :: "r"(_db), "l"(_gb)); \
    }                                                                               \
    asm volatile("cp.async.commit_group;" ::: "memory");                            \
} while (0)

#define GEMM_COMPUTE(a32, b32, NIMAX)                                               \
    _Pragma("unroll")                                                               \
    for (int ks = 0; ks < 2; ++ks) {                                                \
        uint32_t af[2][4];                                                          \
        _Pragma("unroll")                                                           \
        for (int mi = 0; mi < 2; ++mi) {                                            \
            int r0 = wm * 32 + mi * 16 + (lane >> 2);                               \
            af[mi][0] = (a32)[r0 * 20 + ks * 8 + (lane & 3)];                       \
            af[mi][1] = (a32)[(r0 + 8) * 20 + ks * 8 + (lane & 3)];                 \
            af[mi][2] = (a32)[r0 * 20 + ks * 8 + 4 + (lane & 3)];                   \
            af[mi][3] = (a32)[(r0 + 8) * 20 + ks * 8 + 4 + (lane & 3)];             \
        }                                                                           \
        _Pragma("unroll")                                                           \
        for (int ni = 0; ni < (NIMAX); ++ni) {                                      \
            int cn = wn * 64 + ni * 8 + (lane >> 2);                                \
            uint32_t b0 = (b32)[cn * 20 + ks * 8 + (lane & 3)];                     \
            uint32_t b1 = (b32)[cn * 20 + ks * 8 + 4 + (lane & 3)];                 \
            _Pragma("unroll")                                                       \
            for (int mi = 0; mi < 2; ++mi) {                                        \
                asm volatile(                                                       \
                    "mma.sync.aligned.m16n8k16.row.col.f32.bf16.bf16.f32 "          \
                    "{%0,%1,%2,%3}, {%4,%5,%6,%7}, {%8,%9}, {%0,%1,%2,%3};"         \
                    : "+f"(d[mi][ni][0]), "+f"(d[mi][ni][1]),                       \
                      "+f"(d[mi][ni][2]), "+f"(d[mi][ni][3])                        \
                    : "r"(af[mi][0]), "r"(af[mi][1]), "r"(af[mi][2]), "r"(af[mi][3]), \
                      "r"(b0), "r"(b1));                                            \
            }                                                                       \
        }                                                                           \
    }

    ISSUE_STAGE(0, 0);
    ISSUE_STAGE(1, 1);
    const bool tail = (ntile == 7);
    int stg = 0;
    for (int kb = 0; kb < NKB2; ++kb) {
        if (kb <= NKB2 - 2) { asm volatile("cp.async.wait_group 1;" ::: "memory"); }
        else                { asm volatile("cp.async.wait_group 0;" ::: "memory"); }
        __syncthreads();
        const uint32_t* a32 = (const uint32_t*)(gsm + stg * GSTG);
        const uint32_t* b32 = (const uint32_t*)(gsm + stg * GSTG + 10240);
        if (!tail) { GEMM_COMPUTE(a32, b32, 8); }
        else       { GEMM_COMPUTE(a32, b32, 1); }
        if (kb + 2 < NKB2) {
            int ns = stg + 2; if (ns >= 3) ns -= 3;
            ISSUE_STAGE(kb + 2, ns);
        }
        if (++stg == 3) stg = 0;
    }
#undef ISSUE_STAGE
#undef GEMM_COMPUTE

    const float* __restrict__ bih = dir ? bih_b : bih_f;
    float* __restrict__ xg = g_xg[dir];
    const int nimax = tail ? 1 : 8;
#pragma unroll
    for (int mi = 0; mi < 2; ++mi) {
        int r0 = m0 + wm * 32 + mi * 16 + (lane >> 2);
        for (int ni = 0; ni < nimax; ++ni) {
            int g = n0 + wn * 64 + ni * 8 + (lane & 3) * 2;
            if (g < G) {
                float bg0 = bih[g], bg1 = bih[g + 1];
                *(float2*)(xg + (size_t)r0 * G + g) =
                    make_float2(d[mi][ni][0] + bg0, d[mi][ni][1] + bg1);
                *(float2*)(xg + (size_t)(r0 + 8) * G + g) =
                    make_float2(d[mi][ni][2] + bg0, d[mi][ni][3] + bg1);
            }
        }
    }
}

// ---------------- 4) recurrent GRU: xg register-prefetch + early refill ----------------
__global__ void __launch_bounds__(RNT, 1) k_recur_mma(const float* __restrict__ bih_f,
                                                      const float* __restrict__ bih_b,
                                                      const float* __restrict__ bhh_f,
                                                      const float* __restrict__ bhh_b,
                                                      float* __restrict__ out) {
    extern __shared__ char smem[];
    float*           Dsm  = (float*)(smem + SM_D);
    uint32_t*        hs32 = (uint32_t*)(smem + SM_HS);
    __nv_bfloat16*   hsb  = (__nv_bfloat16*)(smem + SM_HS);
    float*           hf   = (float*)(smem + SM_HF);
    float*           sbhh = (float*)(smem + SM_BH);
    float*           sbih = (float*)(smem + SM_BI);
    int*             sst  = (int*)(smem + SM_MISC);
    int*             sln  = sst + RBT;

    const int tid = threadIdx.x, lane = tid & 31, wid = tid >> 5;
    const int dir = blockIdx.y;
    const int b0 = blockIdx.x * RBT;
    // uneven warp tiling: warps 0-8 own 4 m16 tiles, warps 9-15 own 3 (57 total)
    const int ntl   = (wid < 9) ? 4 : 3;
    const int wrow0 = (wid < 9) ? wid * 64 : 576 + (wid - 9) * 48;
    const uint32_t swb = smem_u32(smem);

    uint32_t afro[4];
    {
        int lsel = lane >> 3, lrow = lane & 7;
        int half = lsel >> 1;
#pragma unroll
        for (int i = 0; i < 4; ++i) {
            int row = wrow0 + i * 16 + lrow + ((lsel & 1) << 3);
            afro[i] = row * 32 + ((half ^ ((row >> 2) & 1)) << 4);
        }
    }

    const __nv_bfloat16* __restrict__ gw = g_gwr + (size_t)dir * RKC * RROWS * 16;
    const float* __restrict__ xg = g_xg[dir];

#define ISSUE_WCHUNK(pfc, stg) do {                                                 \
    const char* _src = (const char*)(gw + (size_t)(pfc) * (RROWS * 16)) + wrow0 * 32; \
    const int _nt2 = ntl * 32;                                                      \
    _Pragma("unroll")                                                               \
    for (int _i = 0; _i < 4; ++_i) {                                                \
        int _fl = lane + 32 * _i;                                                   \
        if (_fl < _nt2) {                                                           \
            int _row = _fl >> 1, _half = _fl & 1;                                   \
            int _ar = wrow0 + _row;                                                 \
            int _hsw = _half ^ ((_ar >> 2) & 1);                                    \
            uint32_t _d = swb + (stg) * WSTG + _ar * 32 + (_hsw << 4);              \
            const void* _s = _src + _row * 32 + _half * 16;                         \
            asm volatile("cp.async.cg.shared.global [%0], [%1], 16;" :: "r"(_d), "l"(_s)); \
        }                                                                           \
    }                                                                               \
    asm volatile("cp.async.commit_group;" ::: "memory");                            \
} while (0)

#define MMA_ACC(ac, Af, B0, B1)                                                     \
    asm volatile("mma.sync.aligned.m16n8k16.row.col.f32.bf16.bf16.f32 "             \
        "{%0,%1,%2,%3}, {%4,%5,%6,%7}, {%8,%9}, {%0,%1,%2,%3};"                     \
        : "+f"((ac)[0]), "+f"((ac)[1]), "+f"((ac)[2]), "+f"((ac)[3])                \
        : "r"((Af)[0]), "r"((Af)[1]), "r"((Af)[2]), "r"((Af)[3]), "r"(B0), "r"(B1))

#pragma unroll
    for (int p = 0; p < 4; ++p) ISSUE_WCHUNK(p, p);

    if (tid < RBT) { sst[tid] = g_sstart[b0 + tid]; sln[tid] = g_slen[b0 + tid]; }
    for (int i = tid; i < RBT * (HSS / 2); i += RNT) hs32[i] = 0u;
    {
        const float* bhh = dir ? bhh_b : bhh_f;
        const float* bih = dir ? bih_b : bih_f;
        for (int i = tid; i < G; i += RNT) { sbhh[i] = bhh[i]; sbih[i] = bih[i]; }
    }
    __syncthreads();
    for (int it = tid; it < RBT * H; it += RNT) {
        int j = it >> 4, b = it & 15;
        float v = g_h0[(b0 + b) * H + j];
        hf[b * HFS + j] = v;
        __nv_bfloat16 hi = __float2bfloat16(v);
        hsb[b * HSS + j] = hi;
        hsb[b * HSS + 320 + j] = __float2bfloat16(v - __bfloat162float(hi));
    }
    __syncthreads();

    for (int s = 0; s < LSEQ; ++s) {
        int t = dir ? (LSEQ - 1 - s) : s;

        // ---- prefetch this step's xg slice into registers (hidden under MMA loop) ----
        float xp[PWIT][3];
#pragma unroll
        for (int ii = 0; ii < PWIT; ++ii) {
            int it = tid + ii * RNT;
            if (it < RBT * H) {
                int j = it >> 4, b = it & 15;
                if (t < sln[b]) {
                    const float* xr = xg + (size_t)(sst[b] + t) * G;
                    xp[ii][0] = ldcs(xr + j);
                    xp[ii][1] = ldcs(xr + H + j);
                    xp[ii][2] = ldcs(xr + 2 * H + j);
                } else {
                    xp[ii][0] = sbih[j];
                    xp[ii][1] = sbih[H + j];
                    xp[ii][2] = sbih[2 * H + j];
                }
            }
        }

        float acc[4][2][4];
#pragma unroll
        for (int i = 0; i < 4; ++i)
#pragma unroll
            for (int nt = 0; nt < 2; ++nt)
#pragma unroll
                for (int e = 0; e < 4; ++e) acc[i][nt][e] = 0.f;

        const int sbase = 2 * (s & 1);          // (38*s) mod 4

        // ---- hi chunks 0..18: W_hi x (h_hi + h_lo) ----
#pragma unroll 1
        for (int kc = 0; kc < 19; ++kc) {
            const int stage = (kc + sbase) & 3;
            asm volatile("cp.async.wait_group 3;" ::: "memory");
            const uint32_t wbase = swb + (uint32_t)stage * WSTG;
            const int hk = kc * 8;
            uint32_t A[4][4];
            for (int i = 0; i < ntl; ++i) {
                asm volatile("ldmatrix.sync.aligned.m8n8.x4.shared.b16 "
                             "{%0,%1,%2,%3}, [%4];"
                             : "=r"(A[i][0]), "=r"(A[i][1]), "=r"(A[i][2]), "=r"(A[i][3])
                             : "r"(wbase + afro[i]));
            }
            // refill this stage early (chunk kc+4 for next wrap)
            int pfc = kc + 4; if (pfc >= RKC) pfc -= RKC;
            ISSUE_WCHUNK(pfc, stage);
            uint32_t bh[2][2], bl[2][2];
#pragma unroll
            for (int nt = 0; nt < 2; ++nt) {
                int rb = (nt * 8 + (lane >> 2)) * (HSS / 2);
                bh[nt][0] = hs32[rb + hk + (lane & 3)];
                bh[nt][1] = hs32[rb + hk + 4 + (lane & 3)];
                bl[nt][0] = hs32[rb + 160 + hk + (lane & 3)];
                bl[nt][1] = hs32[rb + 160 + hk + 4 + (lane & 3)];
            }
            for (int i = 0; i < ntl; ++i) {
#pragma unroll
                for (int nt = 0; nt < 2; ++nt)
                    MMA_ACC(acc[i][nt], A[i], bh[nt][0], bh[nt][1]);
            }
            for (int i = 0; i < ntl; ++i) {
#pragma unroll
                for (int nt = 0; nt < 2; ++nt)
                    MMA_ACC(acc[i][nt], A[i], bl[nt][0], bl[nt][1]);
            }
        }
        // ---- lo chunks 19..37: W_lo x h_hi ----
#pragma unroll 1
        for (int kc = 19; kc < RKC; ++kc) {
            const int stage = (kc + sbase) & 3;
            asm volatile("cp.async.wait_group 3;" ::: "memory");
            const uint32_t wbase = swb + (uint32_t)stage * WSTG;
            const int hk = (kc - 19) * 8;
            uint32_t A[4][4];
            for (int i = 0; i < ntl; ++i) {
                asm volatile("ldmatrix.sync.aligned.m8n8.x4.shared.b16 "
                             "{%0,%1,%2,%3}, [%4];"
                             : "=r"(A[i][0]), "=r"(A[i][1]), "=r"(A[i][2]), "=r"(A[i][3])
                             : "r"(wbase + afro[i]));
            }
            int pfc = kc + 4; if (pfc >= RKC) pfc -= RKC;
            ISSUE_WCHUNK(pfc, stage);
            uint32_t bh[2][2];
#pragma unroll
            for (int nt = 0; nt < 2; ++nt) {
                int rb = (nt * 8 + (lane >> 2)) * (HSS / 2);
                bh[nt][0] = hs32[rb + hk + (lane & 3)];
                bh[nt][1] = hs32[rb + hk + 4 + (lane & 3)];
            }
            for (int i = 0; i < ntl; ++i) {
#pragma unroll
                for (int nt = 0; nt < 2; ++nt)
                    MMA_ACC(acc[i][nt], A[i], bh[nt][0], bh[nt][1]);
            }
        }

        // write hg preactivations D[row][graph]
        for (int i = 0; i < ntl; ++i) {
            int r0 = wrow0 + i * 16 + (lane >> 2);
#pragma unroll
            for (int nt = 0; nt < 2; ++nt) {
                int c = nt * 8 + (lane & 3) * 2;
                *(float2*)(Dsm + r0 * 16 + c) = make_float2(acc[i][nt][0], acc[i][nt][1]);
                *(float2*)(Dsm + (r0 + 8) * 16 + c) = make_float2(acc[i][nt][2], acc[i][nt][3]);
            }
        }
        __syncthreads();

        // pointwise GRU update (xg already in registers)
#pragma unroll
        for (int ii = 0; ii < PWIT; ++ii) {
            int it = tid + ii * RNT;
            if (it < RBT * H) {
                int j = it >> 4, b = it & 15;
                bool valid = t < sln[b];
                float hgr = Dsm[j * 16 + b];
                float hgz = Dsm[(GP + j) * 16 + b];
                float hgn = Dsm[(2 * GP + j) * 16 + b];
                float r  = sigm(xp[ii][0] + hgr + sbhh[j]);
                float z  = sigm(xp[ii][1] + hgz + sbhh[H + j]);
                float nn = tanh_fast(xp[ii][2] + r * (hgn + sbhh[2 * H + j]));
                float hp = hf[b * HFS + j];
                float hv = (1.f - z) * nn + z * hp;
                hf[b * HFS + j] = hv;
                __nv_bfloat16 hi = __float2bfloat16(hv);
                hsb[b * HSS + j] = hi;
                hsb[b * HSS + 320 + j] = __float2bfloat16(hv - __bfloat162float(hi));
                if (valid)
                    stcs(out + (size_t)(sst[b] + t) * (2 * H) + dir * H + j, hv);
            }
        }
        __syncthreads();
    }
    asm volatile("cp.async.wait_group 0;" ::: "memory");
#undef ISSUE_WCHUNK
#undef MMA_ACC
}

// ---------------- host entry ----------------
extern "C" void kernel_launch(void* const* d_in, const int* in_sizes, int n_in,
                              void* d_out, int out_size) {
    const float* node   = (const float*)d_in[0];
    const int*   batch  = (const int*)d_in[1];
    const int*   pos    = (const int*)d_in[2];
    const float* bias   = (const float*)d_in[3];
    const float* w_ih_f = (const float*)d_in[4];
    const float* w_hh_f = (const float*)d_in[5];
    const float* b_ih_f = (const float*)d_in[6];
    const float* b_hh_f = (const float*)d_in[7];
    const float* w_ih_b = (const float*)d_in[8];
    const float* w_hh_b = (const float*)d_in[9];
    const float* b_ih_b = (const float*)d_in[10];
    const float* b_hh_b = (const float*)d_in[11];
    float* out = (float*)d_out;
    int n = in_sizes[0] / H;

    cudaFuncSetAttribute(k_gemm_mma, cudaFuncAttributeMaxDynamicSharedMemorySize, GSM_TOT);
    cudaFuncSetAttribute(k_recur_mma, cudaFuncAttributeMaxDynamicSharedMemorySize, SM_TOT);

    int gprep = 64 + n + 512 + 256;
    k_prep<<<gprep, 256>>>(node, bias, batch, pos, w_ih_f, w_ih_b, w_hh_f, w_hh_b, n);
    k_h0<<<NB, NTHREADS>>>(node);
    k_gemm_mma<<<dim3(16, n / MT), 256, GSM_TOT>>>(b_ih_f, b_ih_b);
    k_recur_mma<<<dim3(NB / RBT, 2), RNT, SM_TOT>>>(b_ih_f, b_ih_b, b_hh_f, b_hh_b, out);
}